// round 2
// baseline (speedup 1.0000x reference)
#include <cuda_runtime.h>

#define D   512
#define SEQ 1024
#define BB  4
#define NH  8
#define NL  6
#define FFD 2048
#define VOC 512
#define TOK (BB*SEQ)   // 4096

// ---------------- device scratch (no allocations allowed) ----------------
__device__ float g_x[TOK*D];     // residual stream
__device__ float g_q[TOK*D];
__device__ float g_k[TOK*D];
__device__ float g_v[TOK*D];
__device__ float g_a[TOK*D];     // attention output
__device__ float g_f[TOK*FFD];   // ffn hidden
__device__ float g_t[TOK*D];     // gemm temp
__device__ int   g_idmode;       // 1 = ids are int32, 0 = ids are int64

// ---------------- input_ids dtype detection ----------------
// If ids were serialized as int64 (little-endian) every odd int32 word is the
// high half == 0 (ids in [0,512)). If int32, odd words are real ids and the
// probability all 2048 of them are 0 is nil.
__global__ void detect_ids_kernel(const int* __restrict__ p) {
    __shared__ int any;
    if (threadIdx.x == 0) any = 0;
    __syncthreads();
    int loc = 0;
    for (int i = threadIdx.x; i < 2048; i += blockDim.x) loc |= p[2*i + 1];
    if (loc) atomicOr(&any, 1);
    __syncthreads();
    if (threadIdx.x == 0) g_idmode = any ? 1 : 0;
}

// ---------------- embedding + positional encoding ----------------
__global__ void embed_kernel(const int* __restrict__ ids,
                             const float* __restrict__ emb) {
    int bs = blockIdx.x;                 // 0..4095
    int s  = bs & (SEQ - 1);
    int id = g_idmode ? ids[bs] : ids[2*bs];   // int64 low word
    const float* e = emb + (size_t)id * D;
    float* xr = g_x + (size_t)bs * D;
    const float c = -9.210340371976184f / 512.0f;   // -ln(10000)/D
    for (int d = threadIdx.x; d < D; d += blockDim.x) {
        int i2 = d & ~1;
        float ang = (float)s * expf(c * (float)i2);
        float pe  = (d & 1) ? cosf(ang) : sinf(ang);
        xr[d] = e[d] * 22.627416997969522f + pe;   // sqrt(512)
    }
}

// ---------------- GEMM: C[M,N] = A[M,K] @ W[N,K]^T + bias, opt ReLU ------
// 64x64 tile, BK=32, 256 threads, 4x4 per-thread microtile, double-buffered
// global loads (2 float4 in flight). Operands stored k-major in smem so
// compute loads are contiguous float4 (conflict-free).
__global__ void __launch_bounds__(256) gemm_kernel(
    const float* __restrict__ A, const float* __restrict__ W,
    const float* __restrict__ bias, float* __restrict__ C,
    int M, int N, int K, int relu)
{
    __shared__ float As[32][64];
    __shared__ float Ws[32][64];
    const int tid = threadIdx.x;
    const int tx = tid & 15, ty = tid >> 4;
    const int m0 = blockIdx.y << 6, n0 = blockIdx.x << 6;
    const int lr = tid >> 2;          // 0..63   (row within tile)
    const int lc = (tid & 3) << 3;    // 0,8,16,24 (k-offset, 2 float4 each)
    const float* Ag = A + (size_t)(m0 + lr) * K + lc;
    const float* Wg = W + (size_t)(n0 + lr) * K + lc;
    float acc[4][4] = {};
    for (int k0 = 0; k0 < K; k0 += 32) {
        float4 a0 = *(const float4*)(Ag + k0);
        float4 a1 = *(const float4*)(Ag + k0 + 4);
        float4 w0 = *(const float4*)(Wg + k0);
        float4 w1 = *(const float4*)(Wg + k0 + 4);
        __syncthreads();
        As[lc+0][lr] = a0.x; As[lc+1][lr] = a0.y; As[lc+2][lr] = a0.z; As[lc+3][lr] = a0.w;
        As[lc+4][lr] = a1.x; As[lc+5][lr] = a1.y; As[lc+6][lr] = a1.z; As[lc+7][lr] = a1.w;
        Ws[lc+0][lr] = w0.x; Ws[lc+1][lr] = w0.y; Ws[lc+2][lr] = w0.z; Ws[lc+3][lr] = w0.w;
        Ws[lc+4][lr] = w1.x; Ws[lc+5][lr] = w1.y; Ws[lc+6][lr] = w1.z; Ws[lc+7][lr] = w1.w;
        __syncthreads();
        #pragma unroll
        for (int kk = 0; kk < 32; kk++) {
            float a[4], w[4];
            *(float4*)a = *(const float4*)&As[kk][ty << 2];
            *(float4*)w = *(const float4*)&Ws[kk][tx << 2];
            #pragma unroll
            for (int i = 0; i < 4; i++)
                #pragma unroll
                for (int j = 0; j < 4; j++)
                    acc[i][j] += a[i] * w[j];
        }
    }
    #pragma unroll
    for (int i = 0; i < 4; i++) {
        float4 o;
        float* r = (float*)&o;
        #pragma unroll
        for (int j = 0; j < 4; j++) {
            float v = acc[i][j] + (bias ? bias[n0 + (tx<<2) + j] : 0.0f);
            if (relu) v = fmaxf(v, 0.0f);
            r[j] = v;
        }
        *(float4*)&C[(size_t)(m0 + (ty<<2) + i) * N + n0 + (tx<<2)] = o;
    }
}

// ---------------- flash attention (causal), 64x64 tiles ----------------
// grid: (16 qtiles, B*H). Q/K stored d-major (transposed) in smem, V row-major.
__global__ void __launch_bounds__(256) attn_kernel(
    const float* __restrict__ Qg, const float* __restrict__ Kg,
    const float* __restrict__ Vg, const int* __restrict__ amask,
    float* __restrict__ Og)
{
    extern __shared__ float sm[];
    float* QsT = sm;            // [64][64] d-major
    float* KsT = sm + 4096;     // [64][64] d-major
    float* Vs  = sm + 8192;     // [64][64] row-major (k, d)
    float* Ps  = sm + 12288;    // [64][64]
    const int qt = blockIdx.x, bh = blockIdx.y;
    const int b = bh >> 3, h = bh & 7;
    const int tid = threadIdx.x, tx = tid & 15, ty = tid >> 4;
    const int lr = tid >> 2, lc = (tid & 3) << 4;
    const size_t base = (size_t)b * SEQ * D + h * 64;
    // load Q tile transposed
    {
        const float* Qb = Qg + base + (size_t)(qt*64 + lr) * D + lc;
        #pragma unroll
        for (int j = 0; j < 16; j += 4) {
            float4 v = *(const float4*)(Qb + j);
            QsT[(lc+j+0)*64 + lr] = v.x; QsT[(lc+j+1)*64 + lr] = v.y;
            QsT[(lc+j+2)*64 + lr] = v.z; QsT[(lc+j+3)*64 + lr] = v.w;
        }
    }
    const int* am = amask + b * SEQ;
    float m_i[4] = {-1e30f, -1e30f, -1e30f, -1e30f};
    float l_i[4] = {0.f, 0.f, 0.f, 0.f};
    float o_acc[4][4] = {};
    const int q0 = qt * 64;

    for (int kt = 0; kt <= qt; kt++) {
        __syncthreads();   // previous PV done before overwriting K/V/P tiles
        const float* Kb = Kg + base + (size_t)(kt*64 + lr) * D + lc;
        const float* Vb = Vg + base + (size_t)(kt*64 + lr) * D + lc;
        #pragma unroll
        for (int j = 0; j < 16; j += 4) {
            float4 v = *(const float4*)(Kb + j);
            KsT[(lc+j+0)*64 + lr] = v.x; KsT[(lc+j+1)*64 + lr] = v.y;
            KsT[(lc+j+2)*64 + lr] = v.z; KsT[(lc+j+3)*64 + lr] = v.w;
            float4 u = *(const float4*)(Vb + j);
            *(float4*)&Vs[lr*64 + lc + j] = u;
        }
        __syncthreads();
        // scores S = Q K^T (64x64x64)
        float sc[4][4] = {};
        #pragma unroll 8
        for (int kk = 0; kk < 64; kk++) {
            float a[4], w[4];
            *(float4*)a = *(const float4*)&QsT[kk*64 + (ty<<2)];
            *(float4*)w = *(const float4*)&KsT[kk*64 + (tx<<2)];
            #pragma unroll
            for (int i = 0; i < 4; i++)
                #pragma unroll
                for (int j = 0; j < 4; j++)
                    sc[i][j] += a[i] * w[j];
        }
        const int kbase = kt*64 + (tx<<2);
        int amv[4];
        #pragma unroll
        for (int j = 0; j < 4; j++) amv[j] = am[kbase + j];
        #pragma unroll
        for (int i = 0; i < 4; i++) {
            int qg = q0 + (ty<<2) + i;
            float mx = -1e30f;
            #pragma unroll
            for (int j = 0; j < 4; j++) {
                float v = sc[i][j] * 0.125f;           // 1/sqrt(64)
                if (kbase + j > qg || amv[j] == 0) v = -1e9f;
                sc[i][j] = v;
                mx = fmaxf(mx, v);
            }
            #pragma unroll
            for (int off = 1; off < 16; off <<= 1)
                mx = fmaxf(mx, __shfl_xor_sync(0xffffffffu, mx, off));
            float mn = fmaxf(m_i[i], mx);
            float alpha = expf(m_i[i] - mn);
            float rs = 0.f;
            #pragma unroll
            for (int j = 0; j < 4; j++) {
                float p = expf(sc[i][j] - mn);
                sc[i][j] = p;
                rs += p;
            }
            #pragma unroll
            for (int off = 1; off < 16; off <<= 1)
                rs += __shfl_xor_sync(0xffffffffu, rs, off);
            l_i[i] = l_i[i] * alpha + rs;
            m_i[i] = mn;
            #pragma unroll
            for (int j = 0; j < 4; j++) o_acc[i][j] *= alpha;
            *(float4*)&Ps[((ty<<2)+i)*64 + (tx<<2)] =
                make_float4(sc[i][0], sc[i][1], sc[i][2], sc[i][3]);
        }
        __syncthreads();
        // O += P V (64x64x64)
        #pragma unroll 8
        for (int kk = 0; kk < 64; kk++) {
            float w[4];
            *(float4*)w = *(const float4*)&Vs[kk*64 + (tx<<2)];
            #pragma unroll
            for (int i = 0; i < 4; i++) {
                float a = Ps[((ty<<2)+i)*64 + kk];
                #pragma unroll
                for (int j = 0; j < 4; j++) o_acc[i][j] += a * w[j];
            }
        }
    }
    #pragma unroll
    for (int i = 0; i < 4; i++) {
        float inv = 1.0f / l_i[i];
        *(float4*)&Og[base + (size_t)(q0 + (ty<<2) + i) * D + (tx<<2)] =
            make_float4(o_acc[i][0]*inv, o_acc[i][1]*inv, o_acc[i][2]*inv, o_acc[i][3]*inv);
    }
}

// ---------------- fused (residual add +) LayerNorm, row of 512 ----------
__global__ void add_ln_kernel(float* __restrict__ X, const float* __restrict__ R,
                              const float* __restrict__ g, const float* __restrict__ b)
{
    const int row = blockIdx.x;
    __shared__ float sh[4];
    const int c = threadIdx.x * 4;
    float4 v = *(const float4*)&X[(size_t)row*D + c];
    if (R) {
        float4 r = *(const float4*)&R[(size_t)row*D + c];
        v.x += r.x; v.y += r.y; v.z += r.z; v.w += r.w;
    }
    float s = v.x + v.y + v.z + v.w;
    #pragma unroll
    for (int o = 16; o; o >>= 1) s += __shfl_xor_sync(0xffffffffu, s, o);
    if ((threadIdx.x & 31) == 0) sh[threadIdx.x >> 5] = s;
    __syncthreads();
    float mu = (sh[0] + sh[1] + sh[2] + sh[3]) * (1.0f / D);
    float dx = v.x - mu, dy = v.y - mu, dz = v.z - mu, dw = v.w - mu;
    float sq = dx*dx + dy*dy + dz*dz + dw*dw;
    #pragma unroll
    for (int o = 16; o; o >>= 1) sq += __shfl_xor_sync(0xffffffffu, sq, o);
    __syncthreads();
    if ((threadIdx.x & 31) == 0) sh[threadIdx.x >> 5] = sq;
    __syncthreads();
    float var = (sh[0] + sh[1] + sh[2] + sh[3]) * (1.0f / D);
    float inv = rsqrtf(var + 1e-5f);
    float4 gg = *(const float4*)&g[c];
    float4 bb = *(const float4*)&b[c];
    float4 o;
    o.x = dx*inv*gg.x + bb.x; o.y = dy*inv*gg.y + bb.y;
    o.z = dz*inv*gg.z + bb.z; o.w = dw*inv*gg.w + bb.w;
    *(float4*)&X[(size_t)row*D + c] = o;
}

// ---------------- host orchestration ----------------
extern "C" void kernel_launch(void* const* d_in, const int* in_sizes, int n_in,
                              void* d_out, int out_size)
{
    const int*   ids  = (const int*)  d_in[0];
    const int*   am   = (const int*)  d_in[1];
    const float* emb  = (const float*)d_in[2];
    const float* wq   = (const float*)d_in[3];  const float* bq = (const float*)d_in[4];
    const float* wk   = (const float*)d_in[5];  const float* bk = (const float*)d_in[6];
    const float* wv   = (const float*)d_in[7];  const float* bv = (const float*)d_in[8];
    const float* wo   = (const float*)d_in[9];  const float* bo = (const float*)d_in[10];
    const float* ln1g = (const float*)d_in[11]; const float* ln1b = (const float*)d_in[12];
    const float* w1   = (const float*)d_in[13]; const float* b1 = (const float*)d_in[14];
    const float* w2   = (const float*)d_in[15]; const float* b2 = (const float*)d_in[16];
    const float* ln2g = (const float*)d_in[17]; const float* ln2b = (const float*)d_in[18];
    const float* lnfg = (const float*)d_in[19]; const float* lnfb = (const float*)d_in[20];
    const float* lmw  = (const float*)d_in[21];
    float* out = (float*)d_out;

    // One-time host-side init (pointer queries + attribute set; host memory only)
    static float *xp = nullptr, *qp, *kp, *vp, *ap, *fp, *tp;
    if (!xp) {
        cudaGetSymbolAddress((void**)&xp, g_x);
        cudaGetSymbolAddress((void**)&qp, g_q);
        cudaGetSymbolAddress((void**)&kp, g_k);
        cudaGetSymbolAddress((void**)&vp, g_v);
        cudaGetSymbolAddress((void**)&ap, g_a);
        cudaGetSymbolAddress((void**)&fp, g_f);
        cudaGetSymbolAddress((void**)&tp, g_t);
        cudaFuncSetAttribute(attn_kernel, cudaFuncAttributeMaxDynamicSharedMemorySize, 65536);
    }

    detect_ids_kernel<<<1, 256>>>(ids);
    embed_kernel<<<TOK, 128>>>(ids, emb);

    const dim3 gD(D/64, TOK/64);      // N=512
    const dim3 gF(FFD/64, TOK/64);    // N=2048
    for (int l = 0; l < NL; l++) {
        const size_t dd = (size_t)l * D * D;
        gemm_kernel<<<gD, 256>>>(xp, wq + dd, bq + l*D, qp, TOK, D, D, 0);
        gemm_kernel<<<gD, 256>>>(xp, wk + dd, bk + l*D, kp, TOK, D, D, 0);
        gemm_kernel<<<gD, 256>>>(xp, wv + dd, bv + l*D, vp, TOK, D, D, 0);
        attn_kernel<<<dim3(SEQ/64, BB*NH), 256, 65536>>>(qp, kp, vp, am, ap);
        gemm_kernel<<<gD, 256>>>(ap, wo + dd, bo + l*D, tp, TOK, D, D, 0);
        add_ln_kernel<<<TOK, 128>>>(xp, tp, ln1g + l*D, ln1b + l*D);
        gemm_kernel<<<gF, 256>>>(xp, w1 + (size_t)l*FFD*D, b1 + l*FFD, fp, TOK, FFD, D, 1);
        gemm_kernel<<<gD, 256>>>(fp, w2 + (size_t)l*D*FFD, b2 + l*D, tp, TOK, D, FFD, 0);
        add_ln_kernel<<<TOK, 128>>>(xp, tp, ln2g + l*D, ln2b + l*D);
    }
    add_ln_kernel<<<TOK, 128>>>(xp, nullptr, lnfg, lnfb);
    gemm_kernel<<<gD, 256>>>(xp, lmw, nullptr, out, TOK, VOC, D, 0);
}

// round 3
// speedup vs baseline: 1.1381x; 1.1381x over previous
#include <cuda_runtime.h>

#define D   512
#define SEQ 1024
#define BB  4
#define NH  8
#define NL  6
#define FFD 2048
#define VOC 512
#define TOK (BB*SEQ)   // 4096

// ---------------- device scratch (no allocations allowed) ----------------
__device__ float g_x[TOK*D];     // residual stream
__device__ float g_q[TOK*D];
__device__ float g_k[TOK*D];
__device__ float g_v[TOK*D];
__device__ float g_a[TOK*D];     // attention output
__device__ float g_f[TOK*FFD];   // ffn hidden
__device__ float g_t[TOK*D];     // gemm temp
__device__ int   g_idmode;       // 1 = ids are int32, 0 = ids are int64

// ---------------- input_ids dtype detection ----------------
__global__ void detect_ids_kernel(const int* __restrict__ p) {
    __shared__ int any;
    if (threadIdx.x == 0) any = 0;
    __syncthreads();
    int loc = 0;
    for (int i = threadIdx.x; i < 2048; i += blockDim.x) loc |= p[2*i + 1];
    if (loc) atomicOr(&any, 1);
    __syncthreads();
    if (threadIdx.x == 0) g_idmode = any ? 1 : 0;
}

// ---------------- embedding + positional encoding ----------------
__global__ void embed_kernel(const int* __restrict__ ids,
                             const float* __restrict__ emb) {
    int bs = blockIdx.x;                 // 0..4095
    int s  = bs & (SEQ - 1);
    int id = g_idmode ? ids[bs] : ids[2*bs];   // int64 low word
    const float* e = emb + (size_t)id * D;
    float* xr = g_x + (size_t)bs * D;
    const float c = -9.210340371976184f / 512.0f;   // -ln(10000)/D
    for (int d = threadIdx.x; d < D; d += blockDim.x) {
        int i2 = d & ~1;
        float ang = (float)s * expf(c * (float)i2);
        float pe  = (d & 1) ? cosf(ang) : sinf(ang);
        xr[d] = e[d] * 22.627416997969522f + pe;   // sqrt(512)
    }
}

// ---------------- GEMM: C[M,N] = A[M,K] @ W[N,K]^T + bias, opt ReLU ------
// 128x128 tile, BK=16, 256 threads, 8x8 per-thread microtile (4+4 split with
// 64-offset halves -> A-frag loads broadcast, W-frag loads contiguous).
// Double-buffered smem (one sync/tile), register-prefetched global loads.
// Smem is k-major with pad 132 (16B aligned, conflict-free transposed stores:
// a warp stores 32 consecutive rows at fixed k).
#define BK 16
#define SPAD 132
__global__ void __launch_bounds__(256, 2) gemm_kernel(
    const float* __restrict__ A, const float* __restrict__ W,
    const float* __restrict__ bias, float* __restrict__ C,
    int M, int N, int K, int relu)
{
    __shared__ float As[2][BK][SPAD];
    __shared__ float Ws[2][BK][SPAD];
    const int tid = threadIdx.x;
    const int tx = tid & 15, ty = tid >> 4;
    const int m0 = blockIdx.y << 7, n0 = blockIdx.x << 7;
    const int lrow = tid & 127;          // 0..127 (row within tile)
    const int lk   = (tid >> 7) << 3;    // 0 or 8 (k offset, 8 floats)
    const float* Ag = A + (size_t)(m0 + lrow) * K + lk;
    const float* Wg = W + (size_t)(n0 + lrow) * K + lk;

    float4 pa0, pa1, pw0, pw1;
    pa0 = *(const float4*)(Ag + 0);
    pa1 = *(const float4*)(Ag + 4);
    pw0 = *(const float4*)(Wg + 0);
    pw1 = *(const float4*)(Wg + 4);

    float acc[8][8];
    #pragma unroll
    for (int i = 0; i < 8; i++)
        #pragma unroll
        for (int j = 0; j < 8; j++) acc[i][j] = 0.0f;

    // store tile 0 into buffer 0
    {
        float* as = &As[0][lk][lrow];
        float* ws = &Ws[0][lk][lrow];
        as[0*SPAD] = pa0.x; as[1*SPAD] = pa0.y; as[2*SPAD] = pa0.z; as[3*SPAD] = pa0.w;
        as[4*SPAD] = pa1.x; as[5*SPAD] = pa1.y; as[6*SPAD] = pa1.z; as[7*SPAD] = pa1.w;
        ws[0*SPAD] = pw0.x; ws[1*SPAD] = pw0.y; ws[2*SPAD] = pw0.z; ws[3*SPAD] = pw0.w;
        ws[4*SPAD] = pw1.x; ws[5*SPAD] = pw1.y; ws[6*SPAD] = pw1.z; ws[7*SPAD] = pw1.w;
    }
    __syncthreads();

    int buf = 0;
    for (int k0 = BK; k0 <= K; k0 += BK) {
        if (k0 < K) {                     // prefetch next tile into registers
            pa0 = *(const float4*)(Ag + k0);
            pa1 = *(const float4*)(Ag + k0 + 4);
            pw0 = *(const float4*)(Wg + k0);
            pw1 = *(const float4*)(Wg + k0 + 4);
        }
        // compute current buffer
        #pragma unroll
        for (int kk = 0; kk < BK; kk++) {
            float a[8], w[8];
            *(float4*)(a    ) = *(const float4*)&As[buf][kk][ty << 2];
            *(float4*)(a + 4) = *(const float4*)&As[buf][kk][64 + (ty << 2)];
            *(float4*)(w    ) = *(const float4*)&Ws[buf][kk][tx << 2];
            *(float4*)(w + 4) = *(const float4*)&Ws[buf][kk][64 + (tx << 2)];
            #pragma unroll
            for (int i = 0; i < 8; i++)
                #pragma unroll
                for (int j = 0; j < 8; j++)
                    acc[i][j] += a[i] * w[j];
        }
        if (k0 < K) {                     // stage prefetched tile into other buffer
            float* as = &As[buf ^ 1][lk][lrow];
            float* ws = &Ws[buf ^ 1][lk][lrow];
            as[0*SPAD] = pa0.x; as[1*SPAD] = pa0.y; as[2*SPAD] = pa0.z; as[3*SPAD] = pa0.w;
            as[4*SPAD] = pa1.x; as[5*SPAD] = pa1.y; as[6*SPAD] = pa1.z; as[7*SPAD] = pa1.w;
            ws[0*SPAD] = pw0.x; ws[1*SPAD] = pw0.y; ws[2*SPAD] = pw0.z; ws[3*SPAD] = pw0.w;
            ws[4*SPAD] = pw1.x; ws[5*SPAD] = pw1.y; ws[6*SPAD] = pw1.z; ws[7*SPAD] = pw1.w;
            __syncthreads();
            buf ^= 1;
        }
    }

    // epilogue: rows m0 + {0,64} + ty*4 + i, cols n0 + {0,64} + tx*4
    #pragma unroll
    for (int ih = 0; ih < 2; ih++) {
        #pragma unroll
        for (int i = 0; i < 4; i++) {
            const int row = m0 + ih*64 + (ty << 2) + i;
            #pragma unroll
            for (int jh = 0; jh < 2; jh++) {
                const int col = n0 + jh*64 + (tx << 2);
                float4 o;
                float* r = (float*)&o;
                #pragma unroll
                for (int j = 0; j < 4; j++) {
                    float v = acc[ih*4 + i][jh*4 + j] + (bias ? bias[col + j] : 0.0f);
                    if (relu) v = fmaxf(v, 0.0f);
                    r[j] = v;
                }
                *(float4*)&C[(size_t)row * N + col] = o;
            }
        }
    }
}

// ---------------- flash attention (causal), 64x64 tiles ----------------
__global__ void __launch_bounds__(256) attn_kernel(
    const float* __restrict__ Qg, const float* __restrict__ Kg,
    const float* __restrict__ Vg, const int* __restrict__ amask,
    float* __restrict__ Og)
{
    extern __shared__ float sm[];
    float* QsT = sm;            // [64][64] d-major
    float* KsT = sm + 4096;     // [64][64] d-major
    float* Vs  = sm + 8192;     // [64][64] row-major (k, d)
    float* Ps  = sm + 12288;    // [64][64]
    const int qt = blockIdx.x, bh = blockIdx.y;
    const int b = bh >> 3, h = bh & 7;
    const int tid = threadIdx.x, tx = tid & 15, ty = tid >> 4;
    const int lr = tid >> 2, lc = (tid & 3) << 4;
    const size_t base = (size_t)b * SEQ * D + h * 64;
    {
        const float* Qb = Qg + base + (size_t)(qt*64 + lr) * D + lc;
        #pragma unroll
        for (int j = 0; j < 16; j += 4) {
            float4 v = *(const float4*)(Qb + j);
            QsT[(lc+j+0)*64 + lr] = v.x; QsT[(lc+j+1)*64 + lr] = v.y;
            QsT[(lc+j+2)*64 + lr] = v.z; QsT[(lc+j+3)*64 + lr] = v.w;
        }
    }
    const int* am = amask + b * SEQ;
    float m_i[4] = {-1e30f, -1e30f, -1e30f, -1e30f};
    float l_i[4] = {0.f, 0.f, 0.f, 0.f};
    float o_acc[4][4] = {};
    const int q0 = qt * 64;

    for (int kt = 0; kt <= qt; kt++) {
        __syncthreads();
        const float* Kb = Kg + base + (size_t)(kt*64 + lr) * D + lc;
        const float* Vb = Vg + base + (size_t)(kt*64 + lr) * D + lc;
        #pragma unroll
        for (int j = 0; j < 16; j += 4) {
            float4 v = *(const float4*)(Kb + j);
            KsT[(lc+j+0)*64 + lr] = v.x; KsT[(lc+j+1)*64 + lr] = v.y;
            KsT[(lc+j+2)*64 + lr] = v.z; KsT[(lc+j+3)*64 + lr] = v.w;
            float4 u = *(const float4*)(Vb + j);
            *(float4*)&Vs[lr*64 + lc + j] = u;
        }
        __syncthreads();
        float sc[4][4] = {};
        #pragma unroll 8
        for (int kk = 0; kk < 64; kk++) {
            float a[4], w[4];
            *(float4*)a = *(const float4*)&QsT[kk*64 + (ty<<2)];
            *(float4*)w = *(const float4*)&KsT[kk*64 + (tx<<2)];
            #pragma unroll
            for (int i = 0; i < 4; i++)
                #pragma unroll
                for (int j = 0; j < 4; j++)
                    sc[i][j] += a[i] * w[j];
        }
        const int kbase = kt*64 + (tx<<2);
        int amv[4];
        #pragma unroll
        for (int j = 0; j < 4; j++) amv[j] = am[kbase + j];
        #pragma unroll
        for (int i = 0; i < 4; i++) {
            int qg = q0 + (ty<<2) + i;
            float mx = -1e30f;
            #pragma unroll
            for (int j = 0; j < 4; j++) {
                float v = sc[i][j] * 0.125f;           // 1/sqrt(64)
                if (kbase + j > qg || amv[j] == 0) v = -1e9f;
                sc[i][j] = v;
                mx = fmaxf(mx, v);
            }
            #pragma unroll
            for (int off = 1; off < 16; off <<= 1)
                mx = fmaxf(mx, __shfl_xor_sync(0xffffffffu, mx, off));
            float mn = fmaxf(m_i[i], mx);
            float alpha = expf(m_i[i] - mn);
            float rs = 0.f;
            #pragma unroll
            for (int j = 0; j < 4; j++) {
                float p = expf(sc[i][j] - mn);
                sc[i][j] = p;
                rs += p;
            }
            #pragma unroll
            for (int off = 1; off < 16; off <<= 1)
                rs += __shfl_xor_sync(0xffffffffu, rs, off);
            l_i[i] = l_i[i] * alpha + rs;
            m_i[i] = mn;
            #pragma unroll
            for (int j = 0; j < 4; j++) o_acc[i][j] *= alpha;
            *(float4*)&Ps[((ty<<2)+i)*64 + (tx<<2)] =
                make_float4(sc[i][0], sc[i][1], sc[i][2], sc[i][3]);
        }
        __syncthreads();
        #pragma unroll 8
        for (int kk = 0; kk < 64; kk++) {
            float w[4];
            *(float4*)w = *(const float4*)&Vs[kk*64 + (tx<<2)];
            #pragma unroll
            for (int i = 0; i < 4; i++) {
                float a = Ps[((ty<<2)+i)*64 + kk];
                #pragma unroll
                for (int j = 0; j < 4; j++) o_acc[i][j] += a * w[j];
            }
        }
    }
    #pragma unroll
    for (int i = 0; i < 4; i++) {
        float inv = 1.0f / l_i[i];
        *(float4*)&Og[base + (size_t)(q0 + (ty<<2) + i) * D + (tx<<2)] =
            make_float4(o_acc[i][0]*inv, o_acc[i][1]*inv, o_acc[i][2]*inv, o_acc[i][3]*inv);
    }
}

// ---------------- fused (residual add +) LayerNorm, row of 512 ----------
__global__ void add_ln_kernel(float* __restrict__ X, const float* __restrict__ R,
                              const float* __restrict__ g, const float* __restrict__ b)
{
    const int row = blockIdx.x;
    __shared__ float sh[4];
    const int c = threadIdx.x * 4;
    float4 v = *(const float4*)&X[(size_t)row*D + c];
    if (R) {
        float4 r = *(const float4*)&R[(size_t)row*D + c];
        v.x += r.x; v.y += r.y; v.z += r.z; v.w += r.w;
    }
    float s = v.x + v.y + v.z + v.w;
    #pragma unroll
    for (int o = 16; o; o >>= 1) s += __shfl_xor_sync(0xffffffffu, s, o);
    if ((threadIdx.x & 31) == 0) sh[threadIdx.x >> 5] = s;
    __syncthreads();
    float mu = (sh[0] + sh[1] + sh[2] + sh[3]) * (1.0f / D);
    float dx = v.x - mu, dy = v.y - mu, dz = v.z - mu, dw = v.w - mu;
    float sq = dx*dx + dy*dy + dz*dz + dw*dw;
    #pragma unroll
    for (int o = 16; o; o >>= 1) sq += __shfl_xor_sync(0xffffffffu, sq, o);
    __syncthreads();
    if ((threadIdx.x & 31) == 0) sh[threadIdx.x >> 5] = sq;
    __syncthreads();
    float var = (sh[0] + sh[1] + sh[2] + sh[3]) * (1.0f / D);
    float inv = rsqrtf(var + 1e-5f);
    float4 gg = *(const float4*)&g[c];
    float4 bb = *(const float4*)&b[c];
    float4 o;
    o.x = dx*inv*gg.x + bb.x; o.y = dy*inv*gg.y + bb.y;
    o.z = dz*inv*gg.z + bb.z; o.w = dw*inv*gg.w + bb.w;
    *(float4*)&X[(size_t)row*D + c] = o;
}

// ---------------- host orchestration ----------------
extern "C" void kernel_launch(void* const* d_in, const int* in_sizes, int n_in,
                              void* d_out, int out_size)
{
    const int*   ids  = (const int*)  d_in[0];
    const int*   am   = (const int*)  d_in[1];
    const float* emb  = (const float*)d_in[2];
    const float* wq   = (const float*)d_in[3];  const float* bq = (const float*)d_in[4];
    const float* wk   = (const float*)d_in[5];  const float* bk = (const float*)d_in[6];
    const float* wv   = (const float*)d_in[7];  const float* bv = (const float*)d_in[8];
    const float* wo   = (const float*)d_in[9];  const float* bo = (const float*)d_in[10];
    const float* ln1g = (const float*)d_in[11]; const float* ln1b = (const float*)d_in[12];
    const float* w1   = (const float*)d_in[13]; const float* b1 = (const float*)d_in[14];
    const float* w2   = (const float*)d_in[15]; const float* b2 = (const float*)d_in[16];
    const float* ln2g = (const float*)d_in[17]; const float* ln2b = (const float*)d_in[18];
    const float* lnfg = (const float*)d_in[19]; const float* lnfb = (const float*)d_in[20];
    const float* lmw  = (const float*)d_in[21];
    float* out = (float*)d_out;

    static float *xp = nullptr, *qp, *kp, *vp, *ap, *fp, *tp;
    if (!xp) {
        cudaGetSymbolAddress((void**)&xp, g_x);
        cudaGetSymbolAddress((void**)&qp, g_q);
        cudaGetSymbolAddress((void**)&kp, g_k);
        cudaGetSymbolAddress((void**)&vp, g_v);
        cudaGetSymbolAddress((void**)&ap, g_a);
        cudaGetSymbolAddress((void**)&fp, g_f);
        cudaGetSymbolAddress((void**)&tp, g_t);
        cudaFuncSetAttribute(attn_kernel, cudaFuncAttributeMaxDynamicSharedMemorySize, 65536);
    }

    detect_ids_kernel<<<1, 256>>>(ids);
    embed_kernel<<<TOK, 128>>>(ids, emb);

    const dim3 gD(D/128, TOK/128);      // (4, 32)
    const dim3 gF(FFD/128, TOK/128);    // (16, 32)
    for (int l = 0; l < NL; l++) {
        const size_t dd = (size_t)l * D * D;
        gemm_kernel<<<gD, 256>>>(xp, wq + dd, bq + l*D, qp, TOK, D, D, 0);
        gemm_kernel<<<gD, 256>>>(xp, wk + dd, bk + l*D, kp, TOK, D, D, 0);
        gemm_kernel<<<gD, 256>>>(xp, wv + dd, bv + l*D, vp, TOK, D, D, 0);
        attn_kernel<<<dim3(SEQ/64, BB*NH), 256, 65536>>>(qp, kp, vp, am, ap);
        gemm_kernel<<<gD, 256>>>(ap, wo + dd, bo + l*D, tp, TOK, D, D, 0);
        add_ln_kernel<<<TOK, 128>>>(xp, tp, ln1g + l*D, ln1b + l*D);
        gemm_kernel<<<gF, 256>>>(xp, w1 + (size_t)l*FFD*D, b1 + l*FFD, fp, TOK, FFD, D, 1);
        gemm_kernel<<<gD, 256>>>(fp, w2 + (size_t)l*D*FFD, b2 + l*D, tp, TOK, D, FFD, 0);
        add_ln_kernel<<<TOK, 128>>>(xp, tp, ln2g + l*D, ln2b + l*D);
    }
    add_ln_kernel<<<TOK, 128>>>(xp, nullptr, lnfg, lnfb);
    gemm_kernel<<<gD, 256>>>(xp, lmw, nullptr, out, TOK, VOC, D, 0);
}

// round 5
// speedup vs baseline: 1.8885x; 1.6593x over previous
#include <cuda_runtime.h>
#include <cuda_bf16.h>
#include <cstdint>

#define D   512
#define SEQ 1024
#define BB  4
#define NH  8
#define NL  6
#define FFD 2048
#define VOC 512
#define TOK (BB*SEQ)   // 4096

// ---------------- device scratch (no allocations allowed) ----------------
__device__ float g_x[TOK*D];     // residual stream
__device__ float g_q[TOK*D];
__device__ float g_k[TOK*D];
__device__ float g_v[TOK*D];
__device__ float g_a[TOK*D];     // attention output
__device__ float g_f[TOK*FFD];   // ffn hidden
__device__ float g_t[TOK*D];     // gemm temp
__device__ int   g_idmode;       // 1 = ids are int32, 0 = ids are int64

__device__ __forceinline__ uint32_t smem_u32(const void* p) {
    uint32_t a;
    asm("{ .reg .u64 t; cvta.to.shared.u64 t, %1; cvt.u32.u64 %0, t; }"
        : "=r"(a) : "l"(p));
    return a;
}
__device__ __forceinline__ void ldsm4(uint32_t* r, uint32_t addr) {
    asm volatile("ldmatrix.sync.aligned.m8n8.x4.shared.b16 {%0,%1,%2,%3}, [%4];"
                 : "=r"(r[0]), "=r"(r[1]), "=r"(r[2]), "=r"(r[3]) : "r"(addr));
}
__device__ __forceinline__ void mma_bf16(float* d, const uint32_t* a,
                                         const uint32_t* b) {
    asm volatile("mma.sync.aligned.m16n8k16.row.col.f32.bf16.bf16.f32 "
                 "{%0,%1,%2,%3}, {%4,%5,%6,%7}, {%8,%9}, {%0,%1,%2,%3};"
                 : "+f"(d[0]), "+f"(d[1]), "+f"(d[2]), "+f"(d[3])
                 : "r"(a[0]), "r"(a[1]), "r"(a[2]), "r"(a[3]),
                   "r"(b[0]), "r"(b[1]));
}

// ---------------- input_ids dtype detection ----------------
__global__ void detect_ids_kernel(const int* __restrict__ p) {
    __shared__ int any;
    if (threadIdx.x == 0) any = 0;
    __syncthreads();
    int loc = 0;
    for (int i = threadIdx.x; i < 2048; i += blockDim.x) loc |= p[2*i + 1];
    if (loc) atomicOr(&any, 1);
    __syncthreads();
    if (threadIdx.x == 0) g_idmode = any ? 1 : 0;
}

// ---------------- embedding + positional encoding ----------------
__global__ void embed_kernel(const int* __restrict__ ids,
                             const float* __restrict__ emb) {
    int bs = blockIdx.x;                 // 0..4095
    int s  = bs & (SEQ - 1);
    int id = g_idmode ? ids[bs] : ids[2*bs];   // int64 low word
    const float* e = emb + (size_t)id * D;
    float* xr = g_x + (size_t)bs * D;
    const float c = -9.210340371976184f / 512.0f;   // -ln(10000)/D
    for (int d = threadIdx.x; d < D; d += blockDim.x) {
        int i2 = d & ~1;
        float ang = (float)s * expf(c * (float)i2);
        float pe  = (d & 1) ? cosf(ang) : sinf(ang);
        xr[d] = e[d] * 22.627416997969522f + pe;   // sqrt(512)
    }
}

// =====================================================================
// Tensor-core GEMM via mma.sync bf16 (portable, no sm_100a features):
// C[M,N] = A[M,K] @ W[N,K]^T (+bias, opt ReLU)
// fp32 split to bf16 hi/lo; acc += Ahi*Whi + Alo*Whi + Ahi*Wlo (fp32 acc).
// CTA 128x128, 8 warps of 64x32, K chunks of 64 staged in padded smem.
// =====================================================================
#define SB   72                       // smem row stride in bf16 (144 B)
#define RGB  (128*SB*2)               // bytes per region (18432)
#define GSMEM (4*RGB)                 // Ahi,Alo,Whi,Wlo single buffer (73728)

// stage 128 rows x 64 k of fp32 (row stride ld) into hi/lo bf16 regions
__device__ __forceinline__ void stage_tile(const float* __restrict__ src, int ld,
                                           char* hi, char* lo, int tid) {
    const int r0 = tid >> 2;          // 0..63
    const int kq = (tid & 3) << 4;    // 0,16,32,48
    #pragma unroll
    for (int rr = 0; rr < 128; rr += 64) {
        const int row = rr + r0;
        const float4* s = (const float4*)(src + (size_t)row * ld + kq);
        #pragma unroll
        for (int j = 0; j < 4; j++) {
            float4 v = s[j];
            __nv_bfloat16 h0 = __float2bfloat16(v.x);
            __nv_bfloat16 h1 = __float2bfloat16(v.y);
            __nv_bfloat16 h2 = __float2bfloat16(v.z);
            __nv_bfloat16 h3 = __float2bfloat16(v.w);
            __nv_bfloat16 l0 = __float2bfloat16(v.x - __bfloat162float(h0));
            __nv_bfloat16 l1 = __float2bfloat16(v.y - __bfloat162float(h1));
            __nv_bfloat16 l2 = __float2bfloat16(v.z - __bfloat162float(h2));
            __nv_bfloat16 l3 = __float2bfloat16(v.w - __bfloat162float(h3));
            uint2 hv = make_uint2(
                (uint32_t)__bfloat16_as_ushort(h0) | ((uint32_t)__bfloat16_as_ushort(h1) << 16),
                (uint32_t)__bfloat16_as_ushort(h2) | ((uint32_t)__bfloat16_as_ushort(h3) << 16));
            uint2 lv = make_uint2(
                (uint32_t)__bfloat16_as_ushort(l0) | ((uint32_t)__bfloat16_as_ushort(l1) << 16),
                (uint32_t)__bfloat16_as_ushort(l2) | ((uint32_t)__bfloat16_as_ushort(l3) << 16));
            const int off = row * (SB*2) + (kq + 4*j) * 2;
            *(uint2*)(hi + off) = hv;
            *(uint2*)(lo + off) = lv;
        }
    }
}

__global__ void __launch_bounds__(256) gemm_tc(
    const float* __restrict__ A, const float* __restrict__ W,
    const float* __restrict__ bias, float* __restrict__ C,
    int M, int N, int K, int relu)
{
    extern __shared__ char sm[];
    char* Ahi = sm;            char* Alo = sm + RGB;
    char* Whi = sm + 2*RGB;    char* Wlo = sm + 3*RGB;
    const uint32_t uAhi = smem_u32(Ahi), uAlo = smem_u32(Alo);
    const uint32_t uWhi = smem_u32(Whi), uWlo = smem_u32(Wlo);

    const int tid = threadIdx.x;
    const int wid = tid >> 5, lane = tid & 31;
    const int wm = wid >> 2;          // 0..1 -> m offset 64*wm
    const int wn = wid & 3;           // 0..3 -> n offset 32*wn
    const int m0 = blockIdx.y << 7, n0 = blockIdx.x << 7;

    // ldmatrix lane addressing (byte offsets within a region)
    // A (m16xk16 tile): row = mt*16 + (lane&15); +16B if lane>=16
    const int a_row = lane & 15;
    const int a_kb  = (lane & 16);            // 0 or 16 bytes
    // B (n16xk16 group): row = ng*16 + ((lane>>4)<<3) + (lane&7); +16B if (lane&8)
    const int b_row = ((lane >> 4) << 3) + (lane & 7);
    const int b_kb  = ((lane >> 3) & 1) << 4; // 0 or 16 bytes

    float acc[4][4][4];                        // [mt][n8 tile][4]
    #pragma unroll
    for (int i = 0; i < 4; i++)
        #pragma unroll
        for (int j = 0; j < 4; j++)
            #pragma unroll
            for (int t = 0; t < 4; t++) acc[i][j][t] = 0.0f;

    const int nchunk = K >> 6;
    for (int c = 0; c < nchunk; c++) {
        __syncthreads();                       // prior compute done
        stage_tile(A + (size_t)m0 * K + (c << 6), K, Ahi, Alo, tid);
        stage_tile(W + (size_t)n0 * K + (c << 6), K, Whi, Wlo, tid);
        __syncthreads();
        #pragma unroll
        for (int ks = 0; ks < 4; ks++) {       // k16 steps within chunk
            const int kbyte = ks * 32;
            uint32_t Ah[4][4], Al[4][4];
            #pragma unroll
            for (int mt = 0; mt < 4; mt++) {
                const int roff = (wm*64 + mt*16 + a_row) * (SB*2) + kbyte + a_kb;
                ldsm4(Ah[mt], uAhi + roff);
                ldsm4(Al[mt], uAlo + roff);
            }
            #pragma unroll
            for (int ng = 0; ng < 2; ng++) {   // two n16 groups per warp
                const int roff = (wn*32 + ng*16 + b_row) * (SB*2) + kbyte + b_kb;
                uint32_t Bh[4], Bl[4];
                ldsm4(Bh, uWhi + roff);
                ldsm4(Bl, uWlo + roff);
                #pragma unroll
                for (int mt = 0; mt < 4; mt++) {
                    #pragma unroll
                    for (int half = 0; half < 2; half++) {
                        float* d = acc[mt][ng*2 + half];
                        mma_bf16(d, Ah[mt], Bh + half*2);
                        mma_bf16(d, Al[mt], Bh + half*2);
                        mma_bf16(d, Ah[mt], Bl + half*2);
                    }
                }
            }
        }
    }

    // epilogue: thread (g=lane>>2, tg=lane&3); d0,d1 -> (row g, col 2tg),
    // d2,d3 -> (row g+8, col 2tg)
    const int g = lane >> 2, tg = lane & 3;
    #pragma unroll
    for (int mt = 0; mt < 4; mt++) {
        #pragma unroll
        for (int nt = 0; nt < 4; nt++) {
            const int row = m0 + wm*64 + mt*16 + g;
            const int col = n0 + wn*32 + nt*8 + tg*2;
            float b0 = bias ? bias[col] : 0.0f;
            float b1 = bias ? bias[col+1] : 0.0f;
            float v0 = acc[mt][nt][0] + b0, v1 = acc[mt][nt][1] + b1;
            float v2 = acc[mt][nt][2] + b0, v3 = acc[mt][nt][3] + b1;
            if (relu) {
                v0 = fmaxf(v0, 0.f); v1 = fmaxf(v1, 0.f);
                v2 = fmaxf(v2, 0.f); v3 = fmaxf(v3, 0.f);
            }
            *(float2*)&C[(size_t)row * N + col]       = make_float2(v0, v1);
            *(float2*)&C[(size_t)(row + 8) * N + col] = make_float2(v2, v3);
        }
    }
}

// ---------------- flash attention (causal), 64x64 tiles ----------------
__global__ void __launch_bounds__(256) attn_kernel(
    const float* __restrict__ Qg, const float* __restrict__ Kg,
    const float* __restrict__ Vg, const int* __restrict__ amask,
    float* __restrict__ Og)
{
    extern __shared__ float smf[];
    float* QsT = smf;           // [64][64] d-major
    float* KsT = smf + 4096;    // [64][64] d-major
    float* Vs  = smf + 8192;    // [64][64] row-major (k, d)
    float* Ps  = smf + 12288;   // [64][64]
    const int qt = blockIdx.x, bh = blockIdx.y;
    const int b = bh >> 3, h = bh & 7;
    const int tid = threadIdx.x, tx = tid & 15, ty = tid >> 4;
    const int lr = tid >> 2, lc = (tid & 3) << 4;
    const size_t base = (size_t)b * SEQ * D + h * 64;
    {
        const float* Qb = Qg + base + (size_t)(qt*64 + lr) * D + lc;
        #pragma unroll
        for (int j = 0; j < 16; j += 4) {
            float4 v = *(const float4*)(Qb + j);
            QsT[(lc+j+0)*64 + lr] = v.x; QsT[(lc+j+1)*64 + lr] = v.y;
            QsT[(lc+j+2)*64 + lr] = v.z; QsT[(lc+j+3)*64 + lr] = v.w;
        }
    }
    const int* am = amask + b * SEQ;
    float m_i[4] = {-1e30f, -1e30f, -1e30f, -1e30f};
    float l_i[4] = {0.f, 0.f, 0.f, 0.f};
    float o_acc[4][4] = {};
    const int q0 = qt * 64;

    for (int kt = 0; kt <= qt; kt++) {
        __syncthreads();
        const float* Kb = Kg + base + (size_t)(kt*64 + lr) * D + lc;
        const float* Vb = Vg + base + (size_t)(kt*64 + lr) * D + lc;
        #pragma unroll
        for (int j = 0; j < 16; j += 4) {
            float4 v = *(const float4*)(Kb + j);
            KsT[(lc+j+0)*64 + lr] = v.x; KsT[(lc+j+1)*64 + lr] = v.y;
            KsT[(lc+j+2)*64 + lr] = v.z; KsT[(lc+j+3)*64 + lr] = v.w;
            float4 u = *(const float4*)(Vb + j);
            *(float4*)&Vs[lr*64 + lc + j] = u;
        }
        __syncthreads();
        float sc[4][4] = {};
        #pragma unroll 8
        for (int kk = 0; kk < 64; kk++) {
            float a[4], w[4];
            *(float4*)a = *(const float4*)&QsT[kk*64 + (ty<<2)];
            *(float4*)w = *(const float4*)&KsT[kk*64 + (tx<<2)];
            #pragma unroll
            for (int i = 0; i < 4; i++)
                #pragma unroll
                for (int j = 0; j < 4; j++)
                    sc[i][j] += a[i] * w[j];
        }
        const int kbase = kt*64 + (tx<<2);
        int amv[4];
        #pragma unroll
        for (int j = 0; j < 4; j++) amv[j] = am[kbase + j];
        #pragma unroll
        for (int i = 0; i < 4; i++) {
            int qg = q0 + (ty<<2) + i;
            float mx = -1e30f;
            #pragma unroll
            for (int j = 0; j < 4; j++) {
                float v = sc[i][j] * 0.125f;           // 1/sqrt(64)
                if (kbase + j > qg || amv[j] == 0) v = -1e9f;
                sc[i][j] = v;
                mx = fmaxf(mx, v);
            }
            #pragma unroll
            for (int off = 1; off < 16; off <<= 1)
                mx = fmaxf(mx, __shfl_xor_sync(0xffffffffu, mx, off));
            float mn = fmaxf(m_i[i], mx);
            float alpha = expf(m_i[i] - mn);
            float rs = 0.f;
            #pragma unroll
            for (int j = 0; j < 4; j++) {
                float p = expf(sc[i][j] - mn);
                sc[i][j] = p;
                rs += p;
            }
            #pragma unroll
            for (int off = 1; off < 16; off <<= 1)
                rs += __shfl_xor_sync(0xffffffffu, rs, off);
            l_i[i] = l_i[i] * alpha + rs;
            m_i[i] = mn;
            #pragma unroll
            for (int j = 0; j < 4; j++) o_acc[i][j] *= alpha;
            *(float4*)&Ps[((ty<<2)+i)*64 + (tx<<2)] =
                make_float4(sc[i][0], sc[i][1], sc[i][2], sc[i][3]);
        }
        __syncthreads();
        #pragma unroll 8
        for (int kk = 0; kk < 64; kk++) {
            float w[4];
            *(float4*)w = *(const float4*)&Vs[kk*64 + (tx<<2)];
            #pragma unroll
            for (int i = 0; i < 4; i++) {
                float a = Ps[((ty<<2)+i)*64 + kk];
                #pragma unroll
                for (int j = 0; j < 4; j++) o_acc[i][j] += a * w[j];
            }
        }
    }
    #pragma unroll
    for (int i = 0; i < 4; i++) {
        float inv = 1.0f / l_i[i];
        *(float4*)&Og[base + (size_t)(q0 + (ty<<2) + i) * D + (tx<<2)] =
            make_float4(o_acc[i][0]*inv, o_acc[i][1]*inv, o_acc[i][2]*inv, o_acc[i][3]*inv);
    }
}

// ---------------- fused (residual add +) LayerNorm, row of 512 ----------
__global__ void add_ln_kernel(float* __restrict__ X, const float* __restrict__ R,
                              const float* __restrict__ g, const float* __restrict__ b)
{
    const int row = blockIdx.x;
    __shared__ float sh[4];
    const int c = threadIdx.x * 4;
    float4 v = *(const float4*)&X[(size_t)row*D + c];
    if (R) {
        float4 r = *(const float4*)&R[(size_t)row*D + c];
        v.x += r.x; v.y += r.y; v.z += r.z; v.w += r.w;
    }
    float s = v.x + v.y + v.z + v.w;
    #pragma unroll
    for (int o = 16; o; o >>= 1) s += __shfl_xor_sync(0xffffffffu, s, o);
    if ((threadIdx.x & 31) == 0) sh[threadIdx.x >> 5] = s;
    __syncthreads();
    float mu = (sh[0] + sh[1] + sh[2] + sh[3]) * (1.0f / D);
    float dx = v.x - mu, dy = v.y - mu, dz = v.z - mu, dw = v.w - mu;
    float sq = dx*dx + dy*dy + dz*dz + dw*dw;
    #pragma unroll
    for (int o = 16; o; o >>= 1) sq += __shfl_xor_sync(0xffffffffu, sq, o);
    __syncthreads();
    if ((threadIdx.x & 31) == 0) sh[threadIdx.x >> 5] = sq;
    __syncthreads();
    float var = (sh[0] + sh[1] + sh[2] + sh[3]) * (1.0f / D);
    float inv = rsqrtf(var + 1e-5f);
    float4 gg = *(const float4*)&g[c];
    float4 bb = *(const float4*)&b[c];
    float4 o;
    o.x = dx*inv*gg.x + bb.x; o.y = dy*inv*gg.y + bb.y;
    o.z = dz*inv*gg.z + bb.z; o.w = dw*inv*gg.w + bb.w;
    *(float4*)&X[(size_t)row*D + c] = o;
}

// ---------------- host orchestration ----------------
extern "C" void kernel_launch(void* const* d_in, const int* in_sizes, int n_in,
                              void* d_out, int out_size)
{
    const int*   ids  = (const int*)  d_in[0];
    const int*   am   = (const int*)  d_in[1];
    const float* emb  = (const float*)d_in[2];
    const float* wq   = (const float*)d_in[3];  const float* bq = (const float*)d_in[4];
    const float* wk   = (const float*)d_in[5];  const float* bk = (const float*)d_in[6];
    const float* wv   = (const float*)d_in[7];  const float* bv = (const float*)d_in[8];
    const float* wo   = (const float*)d_in[9];  const float* bo = (const float*)d_in[10];
    const float* ln1g = (const float*)d_in[11]; const float* ln1b = (const float*)d_in[12];
    const float* w1   = (const float*)d_in[13]; const float* b1 = (const float*)d_in[14];
    const float* w2   = (const float*)d_in[15]; const float* b2 = (const float*)d_in[16];
    const float* ln2g = (const float*)d_in[17]; const float* ln2b = (const float*)d_in[18];
    const float* lnfg = (const float*)d_in[19]; const float* lnfb = (const float*)d_in[20];
    const float* lmw  = (const float*)d_in[21];
    float* out = (float*)d_out;

    static float *xp = nullptr, *qp, *kp, *vp, *ap, *fp, *tp;
    if (!xp) {
        cudaGetSymbolAddress((void**)&xp, g_x);
        cudaGetSymbolAddress((void**)&qp, g_q);
        cudaGetSymbolAddress((void**)&kp, g_k);
        cudaGetSymbolAddress((void**)&vp, g_v);
        cudaGetSymbolAddress((void**)&ap, g_a);
        cudaGetSymbolAddress((void**)&fp, g_f);
        cudaGetSymbolAddress((void**)&tp, g_t);
        cudaFuncSetAttribute(attn_kernel, cudaFuncAttributeMaxDynamicSharedMemorySize, 65536);
        cudaFuncSetAttribute(gemm_tc, cudaFuncAttributeMaxDynamicSharedMemorySize, GSMEM);
    }

    detect_ids_kernel<<<1, 256>>>(ids);
    embed_kernel<<<TOK, 128>>>(ids, emb);

    const dim3 gD(D/128, TOK/128);      // (4, 32)
    const dim3 gF(FFD/128, TOK/128);    // (16, 32)
    for (int l = 0; l < NL; l++) {
        const size_t dd = (size_t)l * D * D;
        gemm_tc<<<gD, 256, GSMEM>>>(xp, wq + dd, bq + l*D, qp, TOK, D, D, 0);
        gemm_tc<<<gD, 256, GSMEM>>>(xp, wk + dd, bk + l*D, kp, TOK, D, D, 0);
        gemm_tc<<<gD, 256, GSMEM>>>(xp, wv + dd, bv + l*D, vp, TOK, D, D, 0);
        attn_kernel<<<dim3(SEQ/64, BB*NH), 256, 65536>>>(qp, kp, vp, am, ap);
        gemm_tc<<<gD, 256, GSMEM>>>(ap, wo + dd, bo + l*D, tp, TOK, D, D, 0);
        add_ln_kernel<<<TOK, 128>>>(xp, tp, ln1g + l*D, ln1b + l*D);
        gemm_tc<<<gF, 256, GSMEM>>>(xp, w1 + (size_t)l*FFD*D, b1 + l*FFD, fp, TOK, FFD, D, 1);
        gemm_tc<<<gD, 256, GSMEM>>>(fp, w2 + (size_t)l*D*FFD, b2 + l*D, tp, TOK, D, FFD, 0);
        add_ln_kernel<<<TOK, 128>>>(xp, tp, ln2g + l*D, ln2b + l*D);
    }
    add_ln_kernel<<<TOK, 128>>>(xp, nullptr, lnfg, lnfb);
    gemm_tc<<<gD, 256, GSMEM>>>(xp, lmw, nullptr, out, TOK, VOC, D, 0);
}

// round 6
// speedup vs baseline: 2.1395x; 1.1329x over previous
#include <cuda_runtime.h>
#include <cuda_bf16.h>
#include <cstdint>

#define D   512
#define SEQ 1024
#define BB  4
#define NH  8
#define NL  6
#define FFD 2048
#define VOC 512
#define TOK (BB*SEQ)   // 4096

// weight scratch offsets (element counts into g_wh/g_wl)
#define OFF_WQ 0
#define OFF_WK (6*D*D)
#define OFF_WV (12*D*D)
#define OFF_WO (18*D*D)
#define OFF_W1 (24*D*D)                    // 6291456
#define OFF_W2 (OFF_W1 + 6*FFD*D)          // 12582912
#define OFF_LM (OFF_W2 + 6*D*FFD)          // 18874368
#define W_TOTAL (OFF_LM + VOC*D)           // 19136512

// ---------------- device scratch (no allocations allowed) ----------------
__device__ float g_x[TOK*D];               // residual stream (fp32)
__device__ float g_q[TOK*D];
__device__ float g_k[TOK*D];
__device__ float g_v[TOK*D];
__device__ float g_t[TOK*D];               // gemm temp (fp32)
__device__ __nv_bfloat16 g_xh[TOK*D],  g_xl[TOK*D];    // residual hi/lo
__device__ __nv_bfloat16 g_oh[TOK*D],  g_ol[TOK*D];    // attn out hi/lo
__device__ __nv_bfloat16 g_fh[TOK*FFD], g_fl[TOK*FFD]; // ffn hidden hi/lo
__device__ __nv_bfloat16 g_wh[W_TOTAL], g_wl[W_TOTAL]; // weights hi/lo
__device__ int g_idmode;

// ---------------- helpers ----------------
__device__ __forceinline__ uint32_t smem_u32(const void* p) {
    uint32_t a;
    asm("{ .reg .u64 t; cvta.to.shared.u64 t, %1; cvt.u32.u64 %0, t; }"
        : "=r"(a) : "l"(p));
    return a;
}
__device__ __forceinline__ void ldsm4(uint32_t* r, uint32_t addr) {
    asm volatile("ldmatrix.sync.aligned.m8n8.x4.shared.b16 {%0,%1,%2,%3}, [%4];"
                 : "=r"(r[0]), "=r"(r[1]), "=r"(r[2]), "=r"(r[3]) : "r"(addr));
}
__device__ __forceinline__ void mma_bf16(float* d, const uint32_t* a,
                                         const uint32_t* b) {
    asm volatile("mma.sync.aligned.m16n8k16.row.col.f32.bf16.bf16.f32 "
                 "{%0,%1,%2,%3}, {%4,%5,%6,%7}, {%8,%9}, {%0,%1,%2,%3};"
                 : "+f"(d[0]), "+f"(d[1]), "+f"(d[2]), "+f"(d[3])
                 : "r"(a[0]), "r"(a[1]), "r"(a[2]), "r"(a[3]),
                   "r"(b[0]), "r"(b[1]));
}
#define CPA(dst, src) \
    asm volatile("cp.async.ca.shared.global [%0], [%1], 16;" :: "r"(dst), "l"(src))
#define CPC()  asm volatile("cp.async.commit_group;" ::: "memory")
#define CPW1() asm volatile("cp.async.wait_group 1;" ::: "memory")
#define CPW0() asm volatile("cp.async.wait_group 0;" ::: "memory")

__device__ __forceinline__ uint32_t pack_hi(float a, float b) {
    return (uint32_t)__bfloat16_as_ushort(__float2bfloat16(a)) |
           ((uint32_t)__bfloat16_as_ushort(__float2bfloat16(b)) << 16);
}
__device__ __forceinline__ uint32_t pack_lo(float a, float b) {
    float ra = a - __bfloat162float(__float2bfloat16(a));
    float rb = b - __bfloat162float(__float2bfloat16(b));
    return (uint32_t)__bfloat16_as_ushort(__float2bfloat16(ra)) |
           ((uint32_t)__bfloat16_as_ushort(__float2bfloat16(rb)) << 16);
}

// ---------------- weight conversion: fp32 -> bf16 hi/lo ----------------
__global__ void conv_w(const float* __restrict__ src,
                       __nv_bfloat16* __restrict__ hi,
                       __nv_bfloat16* __restrict__ lo, int n)
{
    int i = (blockIdx.x * 256 + threadIdx.x) * 4;
    if (i >= n) return;
    float4 v = *(const float4*)(src + i);
    *(uint32_t*)&hi[i]     = pack_hi(v.x, v.y);
    *(uint32_t*)&hi[i + 2] = pack_hi(v.z, v.w);
    *(uint32_t*)&lo[i]     = pack_lo(v.x, v.y);
    *(uint32_t*)&lo[i + 2] = pack_lo(v.z, v.w);
}

// ---------------- input_ids dtype detection ----------------
__global__ void detect_ids_kernel(const int* __restrict__ p) {
    __shared__ int any;
    if (threadIdx.x == 0) any = 0;
    __syncthreads();
    int loc = 0;
    for (int i = threadIdx.x; i < 2048; i += blockDim.x) loc |= p[2*i + 1];
    if (loc) atomicOr(&any, 1);
    __syncthreads();
    if (threadIdx.x == 0) g_idmode = any ? 1 : 0;
}

// ---------------- embedding + positional encoding (fp32 + hi/lo) -------
__global__ void embed_kernel(const int* __restrict__ ids,
                             const float* __restrict__ emb) {
    int bs = blockIdx.x;                 // 0..4095
    int s  = bs & (SEQ - 1);
    int id = g_idmode ? ids[bs] : ids[2*bs];
    const float* e = emb + (size_t)id * D;
    const float c = -9.210340371976184f / 512.0f;   // -ln(10000)/D
    const int d0 = threadIdx.x * 4;                 // 128 threads x 4
    float v[4];
    #pragma unroll
    for (int j = 0; j < 4; j++) {
        int d = d0 + j;
        float ang = (float)s * expf(c * (float)(d & ~1));
        float pe  = (d & 1) ? cosf(ang) : sinf(ang);
        v[j] = e[d] * 22.627416997969522f + pe;     // sqrt(512)
    }
    const size_t off = (size_t)bs * D + d0;
    *(float4*)&g_x[off] = make_float4(v[0], v[1], v[2], v[3]);
    *(uint32_t*)&g_xh[off]     = pack_hi(v[0], v[1]);
    *(uint32_t*)&g_xh[off + 2] = pack_hi(v[2], v[3]);
    *(uint32_t*)&g_xl[off]     = pack_lo(v[0], v[1]);
    *(uint32_t*)&g_xl[off + 2] = pack_lo(v[2], v[3]);
}

// =====================================================================
// bf16 tensor-core GEMM with cp.async double-buffered pipeline.
// C[M,N] = A @ W^T (+bias, opt ReLU); A,W pre-split bf16 hi/lo.
// acc += Ah*Wh + Al*Wh + Ah*Wl (fp32 acc). CTA tile 128 x BN, K chunks 32.
// smem row stride 80 B (conflict-free ldmatrix). 8 warps.
// =====================================================================
template<int BN>
__device__ __forceinline__ void load_chunk(
    uint32_t sbuf,
    const __nv_bfloat16* __restrict__ Ah, const __nv_bfloat16* __restrict__ Al,
    const __nv_bfloat16* __restrict__ Wh, const __nv_bfloat16* __restrict__ Wl,
    int m0, int n0, int K, int kc, int tid)
{
    #pragma unroll
    for (int t = 0; t < 4; t++) {               // A: 2 regions x 128 rows x 4 segs
        int s = tid + t * 256;
        int reg = s >> 9;
        int row = (s >> 2) & 127;
        int seg = s & 3;
        uint32_t dst = sbuf + reg * 10240 + row * 80 + seg * 16;
        const __nv_bfloat16* src = (reg ? Al : Ah) + (size_t)(m0 + row) * K + kc + seg * 8;
        CPA(dst, src);
    }
    #pragma unroll
    for (int t = 0; t < BN / 32; t++) {         // W: 2 regions x BN rows x 4 segs
        int s = tid + t * 256;
        int reg = s / (BN * 4);
        int row = (s >> 2) & (BN - 1);
        int seg = s & 3;
        uint32_t dst = sbuf + 20480 + reg * (BN * 80) + row * 80 + seg * 16;
        const __nv_bfloat16* src = (reg ? Wl : Wh) + (size_t)(n0 + row) * K + kc + seg * 8;
        CPA(dst, src);
    }
}

template<int BN>
__global__ void __launch_bounds__(256, 2) gemm_bf(
    const __nv_bfloat16* __restrict__ Ah, const __nv_bfloat16* __restrict__ Al,
    const __nv_bfloat16* __restrict__ Wh, const __nv_bfloat16* __restrict__ Wl,
    const float* __restrict__ bias, float* __restrict__ C,
    __nv_bfloat16* __restrict__ Ch, __nv_bfloat16* __restrict__ Cl,
    int M, int N, int K, int relu)
{
    extern __shared__ char sm[];
    const uint32_t smb = smem_u32(sm);
    constexpr int BUFSZ = 20480 + 2 * BN * 80;
    constexpr int MT = (BN == 64) ? 2 : 4;      // m16 tiles per warp
    const int tid = threadIdx.x, wid = tid >> 5, lane = tid & 31;
    const int wm = (BN == 64) ? (wid >> 1) : (wid >> 2);
    const int wn = (BN == 64) ? (wid & 1) : (wid & 3);
    const int m0 = blockIdx.y << 7;
    const int n0 = blockIdx.x * BN;
    const int a_row = lane & 15,  a_kb = lane & 16;
    const int b_row = ((lane >> 4) << 3) + (lane & 7), b_kb = ((lane >> 3) & 1) << 4;

    float acc[MT][4][4];
    #pragma unroll
    for (int i = 0; i < MT; i++)
        #pragma unroll
        for (int j = 0; j < 4; j++)
            #pragma unroll
            for (int t = 0; t < 4; t++) acc[i][j][t] = 0.0f;

    load_chunk<BN>(smb, Ah, Al, Wh, Wl, m0, n0, K, 0, tid);
    CPC();
    const int nch = K >> 5;
    for (int c = 0; c < nch; c++) {
        const int buf = c & 1;
        if (c + 1 < nch) {
            load_chunk<BN>(smb + (buf ^ 1) * BUFSZ, Ah, Al, Wh, Wl,
                           m0, n0, K, (c + 1) << 5, tid);
            CPC();
            CPW1();
        } else {
            CPW0();
        }
        __syncthreads();
        const uint32_t ab = smb + buf * BUFSZ;
        const uint32_t wb = ab + 20480;
        #pragma unroll
        for (int ks = 0; ks < 2; ks++) {
            const int kbyte = ks * 32;
            uint32_t Bh[2][4], Bl[2][4];
            #pragma unroll
            for (int ng = 0; ng < 2; ng++) {
                const uint32_t roff = (wn*32 + ng*16 + b_row) * 80 + kbyte + b_kb;
                ldsm4(Bh[ng], wb + roff);
                ldsm4(Bl[ng], wb + BN * 80 + roff);
            }
            #pragma unroll
            for (int mt = 0; mt < MT; mt++) {
                uint32_t Af[4], Alf[4];
                const uint32_t aoff = (wm*(MT*16) + mt*16 + a_row) * 80 + kbyte + a_kb;
                ldsm4(Af,  ab + aoff);
                ldsm4(Alf, ab + 10240 + aoff);
                #pragma unroll
                for (int ng = 0; ng < 2; ng++)
                    #pragma unroll
                    for (int hf = 0; hf < 2; hf++) {
                        float* d = acc[mt][ng*2 + hf];
                        mma_bf16(d, Af,  Bh[ng] + hf*2);
                        mma_bf16(d, Alf, Bh[ng] + hf*2);
                        mma_bf16(d, Af,  Bl[ng] + hf*2);
                    }
            }
        }
        __syncthreads();
    }

    const int g = lane >> 2, tg = lane & 3;
    #pragma unroll
    for (int mt = 0; mt < MT; mt++) {
        #pragma unroll
        for (int nt = 0; nt < 4; nt++) {
            const int row = m0 + wm*(MT*16) + mt*16 + g;
            const int col = n0 + wn*32 + nt*8 + tg*2;
            float b0 = bias ? bias[col]     : 0.0f;
            float b1 = bias ? bias[col + 1] : 0.0f;
            float v0 = acc[mt][nt][0] + b0, v1 = acc[mt][nt][1] + b1;
            float v2 = acc[mt][nt][2] + b0, v3 = acc[mt][nt][3] + b1;
            if (relu) {
                v0 = fmaxf(v0, 0.f); v1 = fmaxf(v1, 0.f);
                v2 = fmaxf(v2, 0.f); v3 = fmaxf(v3, 0.f);
            }
            const size_t o0 = (size_t)row * N + col;
            const size_t o1 = (size_t)(row + 8) * N + col;
            if (C) {
                *(float2*)&C[o0] = make_float2(v0, v1);
                *(float2*)&C[o1] = make_float2(v2, v3);
            }
            if (Ch) {
                *(uint32_t*)&Ch[o0] = pack_hi(v0, v1);
                *(uint32_t*)&Ch[o1] = pack_hi(v2, v3);
                *(uint32_t*)&Cl[o0] = pack_lo(v0, v1);
                *(uint32_t*)&Cl[o1] = pack_lo(v2, v3);
            }
        }
    }
}

// ---------------- flash attention (causal), 64x64 tiles ----------------
// writes bf16 hi/lo output only (consumed by WO gemm)
__global__ void __launch_bounds__(256) attn_kernel(
    const float* __restrict__ Qg, const float* __restrict__ Kg,
    const float* __restrict__ Vg, const int* __restrict__ amask,
    __nv_bfloat16* __restrict__ Oh, __nv_bfloat16* __restrict__ Ol)
{
    extern __shared__ float smf[];
    float* QsT = smf;           // [64][64] d-major
    float* KsT = smf + 4096;    // [64][64] d-major
    float* Vs  = smf + 8192;    // [64][64] row-major (k, d)
    float* Ps  = smf + 12288;   // [64][64]
    const int qt = blockIdx.x, bh = blockIdx.y;
    const int b = bh >> 3, h = bh & 7;
    const int tid = threadIdx.x, tx = tid & 15, ty = tid >> 4;
    const int lr = tid >> 2, lc = (tid & 3) << 4;
    const size_t base = (size_t)b * SEQ * D + h * 64;
    {
        const float* Qb = Qg + base + (size_t)(qt*64 + lr) * D + lc;
        #pragma unroll
        for (int j = 0; j < 16; j += 4) {
            float4 v = *(const float4*)(Qb + j);
            QsT[(lc+j+0)*64 + lr] = v.x; QsT[(lc+j+1)*64 + lr] = v.y;
            QsT[(lc+j+2)*64 + lr] = v.z; QsT[(lc+j+3)*64 + lr] = v.w;
        }
    }
    const int* am = amask + b * SEQ;
    float m_i[4] = {-1e30f, -1e30f, -1e30f, -1e30f};
    float l_i[4] = {0.f, 0.f, 0.f, 0.f};
    float o_acc[4][4] = {};
    const int q0 = qt * 64;

    for (int kt = 0; kt <= qt; kt++) {
        __syncthreads();
        const float* Kb = Kg + base + (size_t)(kt*64 + lr) * D + lc;
        const float* Vb = Vg + base + (size_t)(kt*64 + lr) * D + lc;
        #pragma unroll
        for (int j = 0; j < 16; j += 4) {
            float4 v = *(const float4*)(Kb + j);
            KsT[(lc+j+0)*64 + lr] = v.x; KsT[(lc+j+1)*64 + lr] = v.y;
            KsT[(lc+j+2)*64 + lr] = v.z; KsT[(lc+j+3)*64 + lr] = v.w;
            float4 u = *(const float4*)(Vb + j);
            *(float4*)&Vs[lr*64 + lc + j] = u;
        }
        __syncthreads();
        float sc[4][4] = {};
        #pragma unroll 8
        for (int kk = 0; kk < 64; kk++) {
            float a[4], w[4];
            *(float4*)a = *(const float4*)&QsT[kk*64 + (ty<<2)];
            *(float4*)w = *(const float4*)&KsT[kk*64 + (tx<<2)];
            #pragma unroll
            for (int i = 0; i < 4; i++)
                #pragma unroll
                for (int j = 0; j < 4; j++)
                    sc[i][j] += a[i] * w[j];
        }
        const int kbase = kt*64 + (tx<<2);
        int amv[4];
        #pragma unroll
        for (int j = 0; j < 4; j++) amv[j] = am[kbase + j];
        #pragma unroll
        for (int i = 0; i < 4; i++) {
            int qg = q0 + (ty<<2) + i;
            float mx = -1e30f;
            #pragma unroll
            for (int j = 0; j < 4; j++) {
                float v = sc[i][j] * 0.125f;
                if (kbase + j > qg || amv[j] == 0) v = -1e9f;
                sc[i][j] = v;
                mx = fmaxf(mx, v);
            }
            #pragma unroll
            for (int off = 1; off < 16; off <<= 1)
                mx = fmaxf(mx, __shfl_xor_sync(0xffffffffu, mx, off));
            float mn = fmaxf(m_i[i], mx);
            float alpha = expf(m_i[i] - mn);
            float rs = 0.f;
            #pragma unroll
            for (int j = 0; j < 4; j++) {
                float p = expf(sc[i][j] - mn);
                sc[i][j] = p;
                rs += p;
            }
            #pragma unroll
            for (int off = 1; off < 16; off <<= 1)
                rs += __shfl_xor_sync(0xffffffffu, rs, off);
            l_i[i] = l_i[i] * alpha + rs;
            m_i[i] = mn;
            #pragma unroll
            for (int j = 0; j < 4; j++) o_acc[i][j] *= alpha;
            *(float4*)&Ps[((ty<<2)+i)*64 + (tx<<2)] =
                make_float4(sc[i][0], sc[i][1], sc[i][2], sc[i][3]);
        }
        __syncthreads();
        #pragma unroll 8
        for (int kk = 0; kk < 64; kk++) {
            float w[4];
            *(float4*)w = *(const float4*)&Vs[kk*64 + (tx<<2)];
            #pragma unroll
            for (int i = 0; i < 4; i++) {
                float a = Ps[((ty<<2)+i)*64 + kk];
                #pragma unroll
                for (int j = 0; j < 4; j++) o_acc[i][j] += a * w[j];
            }
        }
    }
    #pragma unroll
    for (int i = 0; i < 4; i++) {
        float inv = 1.0f / l_i[i];
        float v0 = o_acc[i][0]*inv, v1 = o_acc[i][1]*inv;
        float v2 = o_acc[i][2]*inv, v3 = o_acc[i][3]*inv;
        const size_t off = base + (size_t)(q0 + (ty<<2) + i) * D + (tx<<2);
        *(uint32_t*)&Oh[off]     = pack_hi(v0, v1);
        *(uint32_t*)&Oh[off + 2] = pack_hi(v2, v3);
        *(uint32_t*)&Ol[off]     = pack_lo(v0, v1);
        *(uint32_t*)&Ol[off + 2] = pack_lo(v2, v3);
    }
}

// ---------------- fused (residual add +) LayerNorm + bf16 split --------
__global__ void add_ln_kernel(float* __restrict__ X, const float* __restrict__ R,
                              const float* __restrict__ g, const float* __restrict__ b,
                              __nv_bfloat16* __restrict__ Xh,
                              __nv_bfloat16* __restrict__ Xl)
{
    const int row = blockIdx.x;
    __shared__ float sh[4];
    const int c = threadIdx.x * 4;
    float4 v = *(const float4*)&X[(size_t)row*D + c];
    if (R) {
        float4 r = *(const float4*)&R[(size_t)row*D + c];
        v.x += r.x; v.y += r.y; v.z += r.z; v.w += r.w;
    }
    float s = v.x + v.y + v.z + v.w;
    #pragma unroll
    for (int o = 16; o; o >>= 1) s += __shfl_xor_sync(0xffffffffu, s, o);
    if ((threadIdx.x & 31) == 0) sh[threadIdx.x >> 5] = s;
    __syncthreads();
    float mu = (sh[0] + sh[1] + sh[2] + sh[3]) * (1.0f / D);
    float dx = v.x - mu, dy = v.y - mu, dz = v.z - mu, dw = v.w - mu;
    float sq = dx*dx + dy*dy + dz*dz + dw*dw;
    #pragma unroll
    for (int o = 16; o; o >>= 1) sq += __shfl_xor_sync(0xffffffffu, sq, o);
    __syncthreads();
    if ((threadIdx.x & 31) == 0) sh[threadIdx.x >> 5] = sq;
    __syncthreads();
    float var = (sh[0] + sh[1] + sh[2] + sh[3]) * (1.0f / D);
    float inv = rsqrtf(var + 1e-5f);
    float4 gg = *(const float4*)&g[c];
    float4 bb = *(const float4*)&b[c];
    float o0 = dx*inv*gg.x + bb.x, o1 = dy*inv*gg.y + bb.y;
    float o2 = dz*inv*gg.z + bb.z, o3 = dw*inv*gg.w + bb.w;
    const size_t off = (size_t)row*D + c;
    *(float4*)&X[off] = make_float4(o0, o1, o2, o3);
    *(uint32_t*)&Xh[off]     = pack_hi(o0, o1);
    *(uint32_t*)&Xh[off + 2] = pack_hi(o2, o3);
    *(uint32_t*)&Xl[off]     = pack_lo(o0, o1);
    *(uint32_t*)&Xl[off + 2] = pack_lo(o2, o3);
}

// ---------------- host orchestration ----------------
extern "C" void kernel_launch(void* const* d_in, const int* in_sizes, int n_in,
                              void* d_out, int out_size)
{
    const int*   ids  = (const int*)  d_in[0];
    const int*   am   = (const int*)  d_in[1];
    const float* emb  = (const float*)d_in[2];
    const float* wq   = (const float*)d_in[3];  const float* bq = (const float*)d_in[4];
    const float* wk   = (const float*)d_in[5];  const float* bk = (const float*)d_in[6];
    const float* wv   = (const float*)d_in[7];  const float* bv = (const float*)d_in[8];
    const float* wo   = (const float*)d_in[9];  const float* bo = (const float*)d_in[10];
    const float* ln1g = (const float*)d_in[11]; const float* ln1b = (const float*)d_in[12];
    const float* w1   = (const float*)d_in[13]; const float* b1 = (const float*)d_in[14];
    const float* w2   = (const float*)d_in[15]; const float* b2 = (const float*)d_in[16];
    const float* ln2g = (const float*)d_in[17]; const float* ln2b = (const float*)d_in[18];
    const float* lnfg = (const float*)d_in[19]; const float* lnfb = (const float*)d_in[20];
    const float* lmw  = (const float*)d_in[21];
    float* out = (float*)d_out;

    static float *xp = nullptr, *qp, *kp, *vp, *tp;
    static __nv_bfloat16 *xh, *xl, *oh, *ol, *fh, *fl, *wh, *wl;
    if (!xp) {
        cudaGetSymbolAddress((void**)&xp, g_x);
        cudaGetSymbolAddress((void**)&qp, g_q);
        cudaGetSymbolAddress((void**)&kp, g_k);
        cudaGetSymbolAddress((void**)&vp, g_v);
        cudaGetSymbolAddress((void**)&tp, g_t);
        cudaGetSymbolAddress((void**)&xh, g_xh);
        cudaGetSymbolAddress((void**)&xl, g_xl);
        cudaGetSymbolAddress((void**)&oh, g_oh);
        cudaGetSymbolAddress((void**)&ol, g_ol);
        cudaGetSymbolAddress((void**)&fh, g_fh);
        cudaGetSymbolAddress((void**)&fl, g_fl);
        cudaGetSymbolAddress((void**)&wh, g_wh);
        cudaGetSymbolAddress((void**)&wl, g_wl);
        cudaFuncSetAttribute(attn_kernel, cudaFuncAttributeMaxDynamicSharedMemorySize, 65536);
        cudaFuncSetAttribute(gemm_bf<64>,  cudaFuncAttributeMaxDynamicSharedMemorySize, 61440);
        cudaFuncSetAttribute(gemm_bf<128>, cudaFuncAttributeMaxDynamicSharedMemorySize, 81920);
    }

    // weight conversion (once per launch)
    conv_w<<<(6*D*D)/1024,   256>>>(wq,  wh + OFF_WQ, wl + OFF_WQ, 6*D*D);
    conv_w<<<(6*D*D)/1024,   256>>>(wk,  wh + OFF_WK, wl + OFF_WK, 6*D*D);
    conv_w<<<(6*D*D)/1024,   256>>>(wv,  wh + OFF_WV, wl + OFF_WV, 6*D*D);
    conv_w<<<(6*D*D)/1024,   256>>>(wo,  wh + OFF_WO, wl + OFF_WO, 6*D*D);
    conv_w<<<(6*FFD*D)/1024, 256>>>(w1,  wh + OFF_W1, wl + OFF_W1, 6*FFD*D);
    conv_w<<<(6*D*FFD)/1024, 256>>>(w2,  wh + OFF_W2, wl + OFF_W2, 6*D*FFD);
    conv_w<<<(VOC*D)/1024,   256>>>(lmw, wh + OFF_LM, wl + OFF_LM, VOC*D);

    detect_ids_kernel<<<1, 256>>>(ids);
    embed_kernel<<<TOK, 128>>>(ids, emb);

    const dim3 gD(D/64,  TOK/128);      // (8, 32)  BN=64
    const dim3 gF(FFD/128, TOK/128);    // (16, 32) BN=128
    for (int l = 0; l < NL; l++) {
        const size_t dd = (size_t)l * D * D;
        gemm_bf<64><<<gD, 256, 61440>>>(xh, xl, wh+OFF_WQ+dd, wl+OFF_WQ+dd,
                                        bq + l*D, qp, nullptr, nullptr, TOK, D, D, 0);
        gemm_bf<64><<<gD, 256, 61440>>>(xh, xl, wh+OFF_WK+dd, wl+OFF_WK+dd,
                                        bk + l*D, kp, nullptr, nullptr, TOK, D, D, 0);
        gemm_bf<64><<<gD, 256, 61440>>>(xh, xl, wh+OFF_WV+dd, wl+OFF_WV+dd,
                                        bv + l*D, vp, nullptr, nullptr, TOK, D, D, 0);
        attn_kernel<<<dim3(SEQ/64, BB*NH), 256, 65536>>>(qp, kp, vp, am, oh, ol);
        gemm_bf<64><<<gD, 256, 61440>>>(oh, ol, wh+OFF_WO+dd, wl+OFF_WO+dd,
                                        bo + l*D, tp, nullptr, nullptr, TOK, D, D, 0);
        add_ln_kernel<<<TOK, 128>>>(xp, tp, ln1g + l*D, ln1b + l*D, xh, xl);
        gemm_bf<128><<<gF, 256, 81920>>>(xh, xl,
                                         wh+OFF_W1+(size_t)l*FFD*D, wl+OFF_W1+(size_t)l*FFD*D,
                                         b1 + l*FFD, nullptr, fh, fl, TOK, FFD, D, 1);
        gemm_bf<64><<<gD, 256, 61440>>>(fh, fl,
                                        wh+OFF_W2+(size_t)l*D*FFD, wl+OFF_W2+(size_t)l*D*FFD,
                                        b2 + l*D, tp, nullptr, nullptr, TOK, D, FFD, 0);
        add_ln_kernel<<<TOK, 128>>>(xp, tp, ln2g + l*D, ln2b + l*D, xh, xl);
    }
    add_ln_kernel<<<TOK, 128>>>(xp, nullptr, lnfg, lnfb, xh, xl);
    gemm_bf<64><<<gD, 256, 61440>>>(xh, xl, wh + OFF_LM, wl + OFF_LM,
                                    nullptr, out, nullptr, nullptr, TOK, VOC, D, 0);
}

// round 7
// speedup vs baseline: 2.7940x; 1.3059x over previous
#include <cuda_runtime.h>
#include <cuda_bf16.h>
#include <cstdint>

#define D   512
#define SEQ 1024
#define BB  4
#define NH  8
#define NL  6
#define FFD 2048
#define VOC 512
#define TOK (BB*SEQ)   // 4096

// weight scratch offsets (element counts into g_wh/g_wl)
#define OFF_WQ 0
#define OFF_WK (6*D*D)
#define OFF_WV (12*D*D)
#define OFF_WO (18*D*D)
#define OFF_W1 (24*D*D)
#define OFF_W2 (OFF_W1 + 6*FFD*D)
#define OFF_LM (OFF_W2 + 6*D*FFD)
#define W_TOTAL (OFF_LM + VOC*D)

// ---------------- device scratch (no allocations allowed) ----------------
__device__ float g_x[TOK*D];               // residual stream (fp32)
__device__ float g_t[TOK*D];               // gemm temp (fp32)
__device__ __nv_bfloat16 g_xh[TOK*D],  g_xl[TOK*D];    // residual hi/lo
__device__ __nv_bfloat16 g_qh[TOK*D],  g_ql[TOK*D];    // Q hi/lo
__device__ __nv_bfloat16 g_kh[TOK*D],  g_kl[TOK*D];    // K hi/lo
__device__ __nv_bfloat16 g_vh[TOK*D],  g_vl[TOK*D];    // V hi/lo
__device__ __nv_bfloat16 g_oh[TOK*D],  g_ol[TOK*D];    // attn out hi/lo
__device__ __nv_bfloat16 g_fh[TOK*FFD], g_fl[TOK*FFD]; // ffn hidden hi/lo
__device__ __nv_bfloat16 g_wh[W_TOTAL], g_wl[W_TOTAL]; // weights hi/lo
__device__ int g_idmode;

// ---------------- helpers ----------------
__device__ __forceinline__ uint32_t smem_u32(const void* p) {
    uint32_t a;
    asm("{ .reg .u64 t; cvta.to.shared.u64 t, %1; cvt.u32.u64 %0, t; }"
        : "=r"(a) : "l"(p));
    return a;
}
__device__ __forceinline__ void ldsm4(uint32_t* r, uint32_t addr) {
    asm volatile("ldmatrix.sync.aligned.m8n8.x4.shared.b16 {%0,%1,%2,%3}, [%4];"
                 : "=r"(r[0]), "=r"(r[1]), "=r"(r[2]), "=r"(r[3]) : "r"(addr));
}
__device__ __forceinline__ void ldsm4t(uint32_t* r, uint32_t addr) {
    asm volatile("ldmatrix.sync.aligned.m8n8.x4.trans.shared.b16 {%0,%1,%2,%3}, [%4];"
                 : "=r"(r[0]), "=r"(r[1]), "=r"(r[2]), "=r"(r[3]) : "r"(addr));
}
__device__ __forceinline__ void mma_bf16(float* d, const uint32_t* a,
                                         const uint32_t* b) {
    asm volatile("mma.sync.aligned.m16n8k16.row.col.f32.bf16.bf16.f32 "
                 "{%0,%1,%2,%3}, {%4,%5,%6,%7}, {%8,%9}, {%0,%1,%2,%3};"
                 : "+f"(d[0]), "+f"(d[1]), "+f"(d[2]), "+f"(d[3])
                 : "r"(a[0]), "r"(a[1]), "r"(a[2]), "r"(a[3]),
                   "r"(b[0]), "r"(b[1]));
}
#define CPA(dst, src) \
    asm volatile("cp.async.ca.shared.global [%0], [%1], 16;" :: "r"(dst), "l"(src))
#define CPC()  asm volatile("cp.async.commit_group;" ::: "memory")
#define CPW1() asm volatile("cp.async.wait_group 1;" ::: "memory")
#define CPW0() asm volatile("cp.async.wait_group 0;" ::: "memory")

__device__ __forceinline__ uint32_t pack_hi(float a, float b) {
    return (uint32_t)__bfloat16_as_ushort(__float2bfloat16(a)) |
           ((uint32_t)__bfloat16_as_ushort(__float2bfloat16(b)) << 16);
}
__device__ __forceinline__ uint32_t pack_lo(float a, float b) {
    float ra = a - __bfloat162float(__float2bfloat16(a));
    float rb = b - __bfloat162float(__float2bfloat16(b));
    return (uint32_t)__bfloat16_as_ushort(__float2bfloat16(ra)) |
           ((uint32_t)__bfloat16_as_ushort(__float2bfloat16(rb)) << 16);
}
// fast exp: 2^(x*log2e) via 5-FMA poly + exponent bit-stuff (no MUFU)
__device__ __forceinline__ float fexp(float x) {
    x = fmaxf(x, -80.0f);
    float t = x * 1.4426950408889634f;
    float fi = rintf(t);
    float f = t - fi;
    float p =              1.3333558146e-3f;
    p = fmaf(p, f, 9.6180209764e-3f);
    p = fmaf(p, f, 5.5504108664e-2f);
    p = fmaf(p, f, 2.4022650695e-1f);
    p = fmaf(p, f, 6.9314718056e-1f);
    p = fmaf(p, f, 1.0f);
    return __int_as_float(((int)fi + 127) << 23) * p;
}

// ---------------- weight conversion: fp32 -> bf16 hi/lo ----------------
__global__ void conv_w(const float* __restrict__ src,
                       __nv_bfloat16* __restrict__ hi,
                       __nv_bfloat16* __restrict__ lo, int n)
{
    int i = (blockIdx.x * 256 + threadIdx.x) * 4;
    if (i >= n) return;
    float4 v = *(const float4*)(src + i);
    *(uint32_t*)&hi[i]     = pack_hi(v.x, v.y);
    *(uint32_t*)&hi[i + 2] = pack_hi(v.z, v.w);
    *(uint32_t*)&lo[i]     = pack_lo(v.x, v.y);
    *(uint32_t*)&lo[i + 2] = pack_lo(v.z, v.w);
}

// ---------------- input_ids dtype detection ----------------
__global__ void detect_ids_kernel(const int* __restrict__ p) {
    __shared__ int any;
    if (threadIdx.x == 0) any = 0;
    __syncthreads();
    int loc = 0;
    for (int i = threadIdx.x; i < 2048; i += blockDim.x) loc |= p[2*i + 1];
    if (loc) atomicOr(&any, 1);
    __syncthreads();
    if (threadIdx.x == 0) g_idmode = any ? 1 : 0;
}

// ---------------- embedding + positional encoding (fp32 + hi/lo) -------
__global__ void embed_kernel(const int* __restrict__ ids,
                             const float* __restrict__ emb) {
    int bs = blockIdx.x;
    int s  = bs & (SEQ - 1);
    int id = g_idmode ? ids[bs] : ids[2*bs];
    const float* e = emb + (size_t)id * D;
    const float c = -9.210340371976184f / 512.0f;
    const int d0 = threadIdx.x * 4;
    float v[4];
    #pragma unroll
    for (int j = 0; j < 4; j++) {
        int d = d0 + j;
        float ang = (float)s * expf(c * (float)(d & ~1));
        float pe  = (d & 1) ? cosf(ang) : sinf(ang);
        v[j] = e[d] * 22.627416997969522f + pe;
    }
    const size_t off = (size_t)bs * D + d0;
    *(float4*)&g_x[off] = make_float4(v[0], v[1], v[2], v[3]);
    *(uint32_t*)&g_xh[off]     = pack_hi(v[0], v[1]);
    *(uint32_t*)&g_xh[off + 2] = pack_hi(v[2], v[3]);
    *(uint32_t*)&g_xl[off]     = pack_lo(v[0], v[1]);
    *(uint32_t*)&g_xl[off + 2] = pack_lo(v[2], v[3]);
}

// =====================================================================
// bf16 tensor-core GEMM with cp.async double-buffered pipeline (R6).
// =====================================================================
template<int BN>
__device__ __forceinline__ void load_chunk(
    uint32_t sbuf,
    const __nv_bfloat16* __restrict__ Ah, const __nv_bfloat16* __restrict__ Al,
    const __nv_bfloat16* __restrict__ Wh, const __nv_bfloat16* __restrict__ Wl,
    int m0, int n0, int K, int kc, int tid)
{
    #pragma unroll
    for (int t = 0; t < 4; t++) {
        int s = tid + t * 256;
        int reg = s >> 9;
        int row = (s >> 2) & 127;
        int seg = s & 3;
        uint32_t dst = sbuf + reg * 10240 + row * 80 + seg * 16;
        const __nv_bfloat16* src = (reg ? Al : Ah) + (size_t)(m0 + row) * K + kc + seg * 8;
        CPA(dst, src);
    }
    #pragma unroll
    for (int t = 0; t < BN / 32; t++) {
        int s = tid + t * 256;
        int reg = s / (BN * 4);
        int row = (s >> 2) & (BN - 1);
        int seg = s & 3;
        uint32_t dst = sbuf + 20480 + reg * (BN * 80) + row * 80 + seg * 16;
        const __nv_bfloat16* src = (reg ? Wl : Wh) + (size_t)(n0 + row) * K + kc + seg * 8;
        CPA(dst, src);
    }
}

template<int BN>
__global__ void __launch_bounds__(256, 2) gemm_bf(
    const __nv_bfloat16* __restrict__ Ah, const __nv_bfloat16* __restrict__ Al,
    const __nv_bfloat16* __restrict__ Wh, const __nv_bfloat16* __restrict__ Wl,
    const float* __restrict__ bias, float* __restrict__ C,
    __nv_bfloat16* __restrict__ Ch, __nv_bfloat16* __restrict__ Cl,
    int M, int N, int K, int relu)
{
    extern __shared__ char sm[];
    const uint32_t smb = smem_u32(sm);
    constexpr int BUFSZ = 20480 + 2 * BN * 80;
    constexpr int MT = (BN == 64) ? 2 : 4;
    const int tid = threadIdx.x, wid = tid >> 5, lane = tid & 31;
    const int wm = (BN == 64) ? (wid >> 1) : (wid >> 2);
    const int wn = (BN == 64) ? (wid & 1) : (wid & 3);
    const int m0 = blockIdx.y << 7;
    const int n0 = blockIdx.x * BN;
    const int a_row = lane & 15,  a_kb = lane & 16;
    const int b_row = ((lane >> 4) << 3) + (lane & 7), b_kb = ((lane >> 3) & 1) << 4;

    float acc[MT][4][4];
    #pragma unroll
    for (int i = 0; i < MT; i++)
        #pragma unroll
        for (int j = 0; j < 4; j++)
            #pragma unroll
            for (int t = 0; t < 4; t++) acc[i][j][t] = 0.0f;

    load_chunk<BN>(smb, Ah, Al, Wh, Wl, m0, n0, K, 0, tid);
    CPC();
    const int nch = K >> 5;
    for (int c = 0; c < nch; c++) {
        const int buf = c & 1;
        if (c + 1 < nch) {
            load_chunk<BN>(smb + (buf ^ 1) * BUFSZ, Ah, Al, Wh, Wl,
                           m0, n0, K, (c + 1) << 5, tid);
            CPC();
            CPW1();
        } else {
            CPW0();
        }
        __syncthreads();
        const uint32_t ab = smb + buf * BUFSZ;
        const uint32_t wb = ab + 20480;
        #pragma unroll
        for (int ks = 0; ks < 2; ks++) {
            const int kbyte = ks * 32;
            uint32_t Bh[2][4], Bl[2][4];
            #pragma unroll
            for (int ng = 0; ng < 2; ng++) {
                const uint32_t roff = (wn*32 + ng*16 + b_row) * 80 + kbyte + b_kb;
                ldsm4(Bh[ng], wb + roff);
                ldsm4(Bl[ng], wb + BN * 80 + roff);
            }
            #pragma unroll
            for (int mt = 0; mt < MT; mt++) {
                uint32_t Af[4], Alf[4];
                const uint32_t aoff = (wm*(MT*16) + mt*16 + a_row) * 80 + kbyte + a_kb;
                ldsm4(Af,  ab + aoff);
                ldsm4(Alf, ab + 10240 + aoff);
                #pragma unroll
                for (int ng = 0; ng < 2; ng++)
                    #pragma unroll
                    for (int hf = 0; hf < 2; hf++) {
                        float* d = acc[mt][ng*2 + hf];
                        mma_bf16(d, Af,  Bh[ng] + hf*2);
                        mma_bf16(d, Alf, Bh[ng] + hf*2);
                        mma_bf16(d, Af,  Bl[ng] + hf*2);
                    }
            }
        }
        __syncthreads();
    }

    const int g = lane >> 2, tg = lane & 3;
    #pragma unroll
    for (int mt = 0; mt < MT; mt++) {
        #pragma unroll
        for (int nt = 0; nt < 4; nt++) {
            const int row = m0 + wm*(MT*16) + mt*16 + g;
            const int col = n0 + wn*32 + nt*8 + tg*2;
            float b0 = bias ? bias[col]     : 0.0f;
            float b1 = bias ? bias[col + 1] : 0.0f;
            float v0 = acc[mt][nt][0] + b0, v1 = acc[mt][nt][1] + b1;
            float v2 = acc[mt][nt][2] + b0, v3 = acc[mt][nt][3] + b1;
            if (relu) {
                v0 = fmaxf(v0, 0.f); v1 = fmaxf(v1, 0.f);
                v2 = fmaxf(v2, 0.f); v3 = fmaxf(v3, 0.f);
            }
            const size_t o0 = (size_t)row * N + col;
            const size_t o1 = (size_t)(row + 8) * N + col;
            if (C) {
                *(float2*)&C[o0] = make_float2(v0, v1);
                *(float2*)&C[o1] = make_float2(v2, v3);
            }
            if (Ch) {
                *(uint32_t*)&Ch[o0] = pack_hi(v0, v1);
                *(uint32_t*)&Ch[o1] = pack_hi(v2, v3);
                *(uint32_t*)&Cl[o0] = pack_lo(v0, v1);
                *(uint32_t*)&Cl[o1] = pack_lo(v2, v3);
            }
        }
    }
}

// =====================================================================
// Tensor-core flash attention (causal): mma.sync bf16 hi/lo.
// CTA: 128 q-rows x (loop of 64 k-cols), 8 warps of m16. Q/K/V bf16 hi/lo
// from producer GEMMs. P stays in registers (score C-frag == PV A-frag).
// smem: Q 2x128x144B, K 2x64x144B, V 2x64x144B, am 256B.
// =====================================================================
#define AQS  0
#define AKS  36864
#define AVS  (36864 + 18432)
#define AAM  (36864 + 36864)
#define ASME (AAM + 256)

__global__ void __launch_bounds__(256) attn_tc(
    const __nv_bfloat16* __restrict__ Qh, const __nv_bfloat16* __restrict__ Ql,
    const __nv_bfloat16* __restrict__ Kh, const __nv_bfloat16* __restrict__ Kl,
    const __nv_bfloat16* __restrict__ Vh, const __nv_bfloat16* __restrict__ Vl,
    const int* __restrict__ amask,
    __nv_bfloat16* __restrict__ Oh, __nv_bfloat16* __restrict__ Ol)
{
    extern __shared__ char sm[];
    const uint32_t smb = smem_u32(sm);
    int* am_s = (int*)(sm + AAM);
    const int qt = blockIdx.x, bh = blockIdx.y;
    const int b = bh >> 3, h = bh & 7;
    const int tid = threadIdx.x, wid = tid >> 5, lane = tid & 31;
    const int g = lane >> 2, tg = lane & 3;
    const size_t base = (size_t)b * SEQ * D + h * 64;
    const int q0 = qt * 128;
    const int a_row = lane & 15, a_kb = lane & 16;
    const int b_row = ((lane >> 4) << 3) + (lane & 7), b_kb = ((lane >> 3) & 1) << 4;
    const int v_row = (((lane >> 3) & 1) << 3) + (lane & 7), v_byte = (lane >> 4) << 4;

    // ---- load Q tile (hi/lo) and pull into register fragments ----
    #pragma unroll
    for (int t = 0; t < 8; t++) {
        int s = tid + t * 256;
        int reg = s >> 10, row = (s >> 3) & 127, seg = s & 7;
        uint32_t dst = smb + AQS + reg * 18432 + row * 144 + seg * 16;
        const __nv_bfloat16* src = (reg ? Ql : Qh) + base + (size_t)(q0 + row) * D + seg * 8;
        CPA(dst, src);
    }
    CPC(); CPW0();
    __syncthreads();
    uint32_t qhf[4][4], qlf[4][4];
    #pragma unroll
    for (int ks = 0; ks < 4; ks++) {
        const uint32_t off = (wid*16 + a_row) * 144 + ks*32 + a_kb;
        ldsm4(qhf[ks], smb + AQS + off);
        ldsm4(qlf[ks], smb + AQS + 18432 + off);
    }

    float m_i[2] = {-1e30f, -1e30f}, l_i[2] = {0.f, 0.f};
    float o_acc[8][4];
    #pragma unroll
    for (int i = 0; i < 8; i++)
        #pragma unroll
        for (int j = 0; j < 4; j++) o_acc[i][j] = 0.f;

    const int row0 = q0 + wid*16 + g;
    const int ktmax = 2*qt + 1;
    for (int kt = 0; kt <= ktmax; kt++) {
        __syncthreads();                      // prev tile's ldsm done
        #pragma unroll
        for (int t = 0; t < 4; t++) {         // K tile hi/lo
            int s = tid + t * 256;
            int reg = s >> 9, row = (s >> 3) & 63, seg = s & 7;
            uint32_t dst = smb + AKS + reg * 9216 + row * 144 + seg * 16;
            const __nv_bfloat16* src = (reg ? Kl : Kh) + base + (size_t)(kt*64 + row) * D + seg * 8;
            CPA(dst, src);
        }
        #pragma unroll
        for (int t = 0; t < 4; t++) {         // V tile hi/lo
            int s = tid + t * 256;
            int reg = s >> 9, row = (s >> 3) & 63, seg = s & 7;
            uint32_t dst = smb + AVS + reg * 9216 + row * 144 + seg * 16;
            const __nv_bfloat16* src = (reg ? Vl : Vh) + base + (size_t)(kt*64 + row) * D + seg * 8;
            CPA(dst, src);
        }
        CPC();
        if (tid < 64) am_s[tid] = amask[b * SEQ + kt*64 + tid];
        CPW0();
        __syncthreads();

        // ---- scores: S = Q K^T (hi/lo 3-term) ----
        float sc[8][4];
        #pragma unroll
        for (int i = 0; i < 8; i++)
            #pragma unroll
            for (int j = 0; j < 4; j++) sc[i][j] = 0.f;
        #pragma unroll
        for (int ks = 0; ks < 4; ks++) {
            #pragma unroll
            for (int ng = 0; ng < 4; ng++) {
                uint32_t Bh[4], Bl[4];
                const uint32_t roff = (ng*16 + b_row) * 144 + ks*32 + b_kb;
                ldsm4(Bh, smb + AKS + roff);
                ldsm4(Bl, smb + AKS + 9216 + roff);
                #pragma unroll
                for (int hf = 0; hf < 2; hf++) {
                    float* d = sc[ng*2 + hf];
                    mma_bf16(d, qhf[ks], Bh + hf*2);
                    mma_bf16(d, qlf[ks], Bh + hf*2);
                    mma_bf16(d, qhf[ks], Bl + hf*2);
                }
            }
        }
        // ---- mask + scale + online softmax ----
        float mx0 = -1e30f, mx1 = -1e30f;
        #pragma unroll
        for (int nt = 0; nt < 8; nt++) {
            const int c0 = nt*8 + tg*2, c1 = c0 + 1;
            const int col0 = kt*64 + c0, col1 = col0 + 1;
            const int ok0 = am_s[c0], ok1 = am_s[c1];
            float s0 = sc[nt][0] * 0.125f, s1 = sc[nt][1] * 0.125f;
            float s2 = sc[nt][2] * 0.125f, s3 = sc[nt][3] * 0.125f;
            if (col0 > row0     || !ok0) s0 = -1e9f;
            if (col1 > row0     || !ok1) s1 = -1e9f;
            if (col0 > row0 + 8 || !ok0) s2 = -1e9f;
            if (col1 > row0 + 8 || !ok1) s3 = -1e9f;
            sc[nt][0] = s0; sc[nt][1] = s1; sc[nt][2] = s2; sc[nt][3] = s3;
            mx0 = fmaxf(mx0, fmaxf(s0, s1));
            mx1 = fmaxf(mx1, fmaxf(s2, s3));
        }
        mx0 = fmaxf(mx0, __shfl_xor_sync(0xffffffffu, mx0, 1));
        mx0 = fmaxf(mx0, __shfl_xor_sync(0xffffffffu, mx0, 2));
        mx1 = fmaxf(mx1, __shfl_xor_sync(0xffffffffu, mx1, 1));
        mx1 = fmaxf(mx1, __shfl_xor_sync(0xffffffffu, mx1, 2));
        const float mn0 = fmaxf(m_i[0], mx0), mn1 = fmaxf(m_i[1], mx1);
        const float al0 = fexp(m_i[0] - mn0), al1 = fexp(m_i[1] - mn1);
        float rs0 = 0.f, rs1 = 0.f;
        #pragma unroll
        for (int nt = 0; nt < 8; nt++) {
            float p0 = fexp(sc[nt][0] - mn0), p1 = fexp(sc[nt][1] - mn0);
            float p2 = fexp(sc[nt][2] - mn1), p3 = fexp(sc[nt][3] - mn1);
            sc[nt][0] = p0; sc[nt][1] = p1; sc[nt][2] = p2; sc[nt][3] = p3;
            rs0 += p0 + p1; rs1 += p2 + p3;
        }
        rs0 += __shfl_xor_sync(0xffffffffu, rs0, 1);
        rs0 += __shfl_xor_sync(0xffffffffu, rs0, 2);
        rs1 += __shfl_xor_sync(0xffffffffu, rs1, 1);
        rs1 += __shfl_xor_sync(0xffffffffu, rs1, 2);
        l_i[0] = l_i[0] * al0 + rs0;  m_i[0] = mn0;
        l_i[1] = l_i[1] * al1 + rs1;  m_i[1] = mn1;
        #pragma unroll
        for (int dt = 0; dt < 8; dt++) {
            o_acc[dt][0] *= al0; o_acc[dt][1] *= al0;
            o_acc[dt][2] *= al1; o_acc[dt][3] *= al1;
        }
        // ---- PV: O += P V (P frags from registers, V via ldmatrix.trans) ----
        #pragma unroll
        for (int ks = 0; ks < 4; ks++) {
            uint32_t ph[4], pl[4];
            const int n0t = 2*ks, n1t = 2*ks + 1;
            ph[0] = pack_hi(sc[n0t][0], sc[n0t][1]); ph[1] = pack_hi(sc[n0t][2], sc[n0t][3]);
            ph[2] = pack_hi(sc[n1t][0], sc[n1t][1]); ph[3] = pack_hi(sc[n1t][2], sc[n1t][3]);
            pl[0] = pack_lo(sc[n0t][0], sc[n0t][1]); pl[1] = pack_lo(sc[n0t][2], sc[n0t][3]);
            pl[2] = pack_lo(sc[n1t][0], sc[n1t][1]); pl[3] = pack_lo(sc[n1t][2], sc[n1t][3]);
            #pragma unroll
            for (int dg = 0; dg < 4; dg++) {
                uint32_t Vhf[4], Vlf[4];
                const uint32_t voff = (ks*16 + v_row) * 144 + dg*32 + v_byte;
                ldsm4t(Vhf, smb + AVS + voff);
                ldsm4t(Vlf, smb + AVS + 9216 + voff);
                #pragma unroll
                for (int hf = 0; hf < 2; hf++) {
                    float* d = o_acc[dg*2 + hf];
                    mma_bf16(d, ph, Vhf + hf*2);
                    mma_bf16(d, pl, Vhf + hf*2);
                    mma_bf16(d, ph, Vlf + hf*2);
                }
            }
        }
    }
    // ---- epilogue ----
    const float inv0 = 1.0f / l_i[0], inv1 = 1.0f / l_i[1];
    #pragma unroll
    for (int dt = 0; dt < 8; dt++) {
        const int col = dt*8 + tg*2;
        const size_t o0 = base + (size_t)row0 * D + col;
        const size_t o1 = base + (size_t)(row0 + 8) * D + col;
        float v0 = o_acc[dt][0]*inv0, v1 = o_acc[dt][1]*inv0;
        float v2 = o_acc[dt][2]*inv1, v3 = o_acc[dt][3]*inv1;
        *(uint32_t*)&Oh[o0] = pack_hi(v0, v1);
        *(uint32_t*)&Oh[o1] = pack_hi(v2, v3);
        *(uint32_t*)&Ol[o0] = pack_lo(v0, v1);
        *(uint32_t*)&Ol[o1] = pack_lo(v2, v3);
    }
}

// ---------------- fused (residual add +) LayerNorm + bf16 split --------
__global__ void add_ln_kernel(float* __restrict__ X, const float* __restrict__ R,
                              const float* __restrict__ g, const float* __restrict__ b,
                              __nv_bfloat16* __restrict__ Xh,
                              __nv_bfloat16* __restrict__ Xl)
{
    const int row = blockIdx.x;
    __shared__ float sh[4];
    const int c = threadIdx.x * 4;
    float4 v = *(const float4*)&X[(size_t)row*D + c];
    if (R) {
        float4 r = *(const float4*)&R[(size_t)row*D + c];
        v.x += r.x; v.y += r.y; v.z += r.z; v.w += r.w;
    }
    float s = v.x + v.y + v.z + v.w;
    #pragma unroll
    for (int o = 16; o; o >>= 1) s += __shfl_xor_sync(0xffffffffu, s, o);
    if ((threadIdx.x & 31) == 0) sh[threadIdx.x >> 5] = s;
    __syncthreads();
    float mu = (sh[0] + sh[1] + sh[2] + sh[3]) * (1.0f / D);
    float dx = v.x - mu, dy = v.y - mu, dz = v.z - mu, dw = v.w - mu;
    float sq = dx*dx + dy*dy + dz*dz + dw*dw;
    #pragma unroll
    for (int o = 16; o; o >>= 1) sq += __shfl_xor_sync(0xffffffffu, sq, o);
    __syncthreads();
    if ((threadIdx.x & 31) == 0) sh[threadIdx.x >> 5] = sq;
    __syncthreads();
    float var = (sh[0] + sh[1] + sh[2] + sh[3]) * (1.0f / D);
    float inv = rsqrtf(var + 1e-5f);
    float4 gg = *(const float4*)&g[c];
    float4 bb = *(const float4*)&b[c];
    float o0 = dx*inv*gg.x + bb.x, o1 = dy*inv*gg.y + bb.y;
    float o2 = dz*inv*gg.z + bb.z, o3 = dw*inv*gg.w + bb.w;
    const size_t off = (size_t)row*D + c;
    *(float4*)&X[off] = make_float4(o0, o1, o2, o3);
    *(uint32_t*)&Xh[off]     = pack_hi(o0, o1);
    *(uint32_t*)&Xh[off + 2] = pack_hi(o2, o3);
    *(uint32_t*)&Xl[off]     = pack_lo(o0, o1);
    *(uint32_t*)&Xl[off + 2] = pack_lo(o2, o3);
}

// ---------------- host orchestration ----------------
extern "C" void kernel_launch(void* const* d_in, const int* in_sizes, int n_in,
                              void* d_out, int out_size)
{
    const int*   ids  = (const int*)  d_in[0];
    const int*   am   = (const int*)  d_in[1];
    const float* emb  = (const float*)d_in[2];
    const float* wq   = (const float*)d_in[3];  const float* bq = (const float*)d_in[4];
    const float* wk   = (const float*)d_in[5];  const float* bk = (const float*)d_in[6];
    const float* wv   = (const float*)d_in[7];  const float* bv = (const float*)d_in[8];
    const float* wo   = (const float*)d_in[9];  const float* bo = (const float*)d_in[10];
    const float* ln1g = (const float*)d_in[11]; const float* ln1b = (const float*)d_in[12];
    const float* w1   = (const float*)d_in[13]; const float* b1 = (const float*)d_in[14];
    const float* w2   = (const float*)d_in[15]; const float* b2 = (const float*)d_in[16];
    const float* ln2g = (const float*)d_in[17]; const float* ln2b = (const float*)d_in[18];
    const float* lnfg = (const float*)d_in[19]; const float* lnfb = (const float*)d_in[20];
    const float* lmw  = (const float*)d_in[21];
    float* out = (float*)d_out;

    static float *xp = nullptr, *tp;
    static __nv_bfloat16 *xh, *xl, *qh, *ql, *kh, *kl, *vh, *vl, *oh, *ol, *fh, *fl, *wh, *wl;
    if (!xp) {
        cudaGetSymbolAddress((void**)&xp, g_x);
        cudaGetSymbolAddress((void**)&tp, g_t);
        cudaGetSymbolAddress((void**)&xh, g_xh);
        cudaGetSymbolAddress((void**)&xl, g_xl);
        cudaGetSymbolAddress((void**)&qh, g_qh);
        cudaGetSymbolAddress((void**)&ql, g_ql);
        cudaGetSymbolAddress((void**)&kh, g_kh);
        cudaGetSymbolAddress((void**)&kl, g_kl);
        cudaGetSymbolAddress((void**)&vh, g_vh);
        cudaGetSymbolAddress((void**)&vl, g_vl);
        cudaGetSymbolAddress((void**)&oh, g_oh);
        cudaGetSymbolAddress((void**)&ol, g_ol);
        cudaGetSymbolAddress((void**)&fh, g_fh);
        cudaGetSymbolAddress((void**)&fl, g_fl);
        cudaGetSymbolAddress((void**)&wh, g_wh);
        cudaGetSymbolAddress((void**)&wl, g_wl);
        cudaFuncSetAttribute(attn_tc, cudaFuncAttributeMaxDynamicSharedMemorySize, ASME);
        cudaFuncSetAttribute(gemm_bf<64>,  cudaFuncAttributeMaxDynamicSharedMemorySize, 61440);
        cudaFuncSetAttribute(gemm_bf<128>, cudaFuncAttributeMaxDynamicSharedMemorySize, 81920);
    }

    conv_w<<<(6*D*D)/1024,   256>>>(wq,  wh + OFF_WQ, wl + OFF_WQ, 6*D*D);
    conv_w<<<(6*D*D)/1024,   256>>>(wk,  wh + OFF_WK, wl + OFF_WK, 6*D*D);
    conv_w<<<(6*D*D)/1024,   256>>>(wv,  wh + OFF_WV, wl + OFF_WV, 6*D*D);
    conv_w<<<(6*D*D)/1024,   256>>>(wo,  wh + OFF_WO, wl + OFF_WO, 6*D*D);
    conv_w<<<(6*FFD*D)/1024, 256>>>(w1,  wh + OFF_W1, wl + OFF_W1, 6*FFD*D);
    conv_w<<<(6*D*FFD)/1024, 256>>>(w2,  wh + OFF_W2, wl + OFF_W2, 6*D*FFD);
    conv_w<<<(VOC*D)/1024,   256>>>(lmw, wh + OFF_LM, wl + OFF_LM, VOC*D);

    detect_ids_kernel<<<1, 256>>>(ids);
    embed_kernel<<<TOK, 128>>>(ids, emb);

    const dim3 gD(D/64,  TOK/128);      // (8, 32)  BN=64
    const dim3 gF(FFD/128, TOK/128);    // (16, 32) BN=128
    for (int l = 0; l < NL; l++) {
        const size_t dd = (size_t)l * D * D;
        gemm_bf<64><<<gD, 256, 61440>>>(xh, xl, wh+OFF_WQ+dd, wl+OFF_WQ+dd,
                                        bq + l*D, nullptr, qh, ql, TOK, D, D, 0);
        gemm_bf<64><<<gD, 256, 61440>>>(xh, xl, wh+OFF_WK+dd, wl+OFF_WK+dd,
                                        bk + l*D, nullptr, kh, kl, TOK, D, D, 0);
        gemm_bf<64><<<gD, 256, 61440>>>(xh, xl, wh+OFF_WV+dd, wl+OFF_WV+dd,
                                        bv + l*D, nullptr, vh, vl, TOK, D, D, 0);
        attn_tc<<<dim3(SEQ/128, BB*NH), 256, ASME>>>(qh, ql, kh, kl, vh, vl, am, oh, ol);
        gemm_bf<64><<<gD, 256, 61440>>>(oh, ol, wh+OFF_WO+dd, wl+OFF_WO+dd,
                                        bo + l*D, tp, nullptr, nullptr, TOK, D, D, 0);
        add_ln_kernel<<<TOK, 128>>>(xp, tp, ln1g + l*D, ln1b + l*D, xh, xl);
        gemm_bf<128><<<gF, 256, 81920>>>(xh, xl,
                                         wh+OFF_W1+(size_t)l*FFD*D, wl+OFF_W1+(size_t)l*FFD*D,
                                         b1 + l*FFD, nullptr, fh, fl, TOK, FFD, D, 1);
        gemm_bf<64><<<gD, 256, 61440>>>(fh, fl,
                                        wh+OFF_W2+(size_t)l*D*FFD, wl+OFF_W2+(size_t)l*D*FFD,
                                        b2 + l*D, tp, nullptr, nullptr, TOK, D, FFD, 0);
        add_ln_kernel<<<TOK, 128>>>(xp, tp, ln2g + l*D, ln2b + l*D, xh, xl);
    }
    add_ln_kernel<<<TOK, 128>>>(xp, nullptr, lnfg, lnfb, xh, xl);
    gemm_bf<64><<<gD, 256, 61440>>>(xh, xl, wh + OFF_LM, wl + OFF_LM,
                                    nullptr, out, nullptr, nullptr, TOK, VOC, D, 0);
}